// round 3
// baseline (speedup 1.0000x reference)
#include <cuda_runtime.h>
#include <cstdint>

#define NTOK 4096            // d*h*w = 16^3
#define CCH  256             // channels
#define BATCH 2
#define GRP  32
#define CPG  (CCH/GRP)       // 8
#define EPSV 1e-6f
#define SCALE 0.0625f        // 256^-0.5

// ---------------- scratch (device globals; no allocation allowed) ----------
__device__ float g_hn[BATCH*CCH*NTOK];
__device__ float g_q [BATCH*CCH*NTOK];
__device__ float g_k [BATCH*CCH*NTOK];
__device__ float g_v [BATCH*CCH*NTOK];
__device__ float g_hv[BATCH*CCH*NTOK];
__device__ float g_p [(size_t)BATCH*NTOK*NTOK];   // 128 MB attention matrix

// ---------------- GroupNorm: one block per (b,g) ---------------------------
__global__ void gn_kernel(const float* __restrict__ x,
                          const float* __restrict__ gamma,
                          const float* __restrict__ beta,
                          float* __restrict__ hn)
{
    const int b = blockIdx.x >> 5;
    const int g = blockIdx.x & 31;
    const float* xp = x  + ((size_t)b*CCH + g*CPG) * NTOK;
    float*       hp = hn + ((size_t)b*CCH + g*CPG) * NTOK;
    const int tid = threadIdx.x;
    const int NEL = CPG * NTOK;            // 32768

    float s = 0.f, ss = 0.f;
    for (int i = tid*4; i < NEL; i += 1024) {
        float4 t = *(const float4*)(xp + i);
        s  += t.x + t.y + t.z + t.w;
        ss += t.x*t.x + t.y*t.y + t.z*t.z + t.w*t.w;
    }
    __shared__ float rs[256], rq[256];
    rs[tid] = s; rq[tid] = ss;
    __syncthreads();
    for (int off = 128; off; off >>= 1) {
        if (tid < off) { rs[tid] += rs[tid+off]; rq[tid] += rq[tid+off]; }
        __syncthreads();
    }
    const float mu   = rs[0] * (1.f/NEL);
    const float var  = rq[0] * (1.f/NEL) - mu*mu;
    const float rstd = rsqrtf(var + EPSV);

    for (int i = tid*4; i < NEL; i += 1024) {
        const int c = g*CPG + (i >> 12);   // 4096 elems per channel
        const float ga = gamma[c]*rstd, be = beta[c];
        float4 t = *(const float4*)(xp + i);
        float4 o;
        o.x = (t.x - mu)*ga + be;
        o.y = (t.y - mu)*ga + be;
        o.z = (t.z - mu)*ga + be;
        o.w = (t.w - mu)*ga + be;
        *(float4*)(hp + i) = o;
    }
}

// ---------------- C[o][n] = W[o][:] . H[:][n] (+bias)(+residual) -----------
// W: 256x256 row-major (K contiguous) -> transposed smem load
// H: 256x4096 (N contiguous)          -> direct smem load
// tile 128x128x8, 256 threads, 8x8 per thread
__global__ void gemm_wh(const float* __restrict__ W,
                        const float* __restrict__ bias,
                        const float* __restrict__ Hbase,
                        float* __restrict__ Obase,
                        int addRes,
                        const float* __restrict__ Xbase)
{
    const int b  = blockIdx.z;
    const float* H = Hbase + (size_t)b*CCH*NTOK;
    float*       O = Obase + (size_t)b*CCH*NTOK;
    const float* X = addRes ? (Xbase + (size_t)b*CCH*NTOK) : nullptr;
    const int o0 = blockIdx.y * 128;
    const int n0 = blockIdx.x * 128;

    __shared__ float Ws[8][132];
    __shared__ float Hs[8][128];

    const int tid = threadIdx.x;
    const int tx = tid & 15, ty = tid >> 4;
    const int wr = tid >> 1, wk = (tid & 1) * 4;
    const int hk = tid >> 5, hc = (tid & 31) * 4;

    float acc[8][8] = {};

    for (int k0 = 0; k0 < CCH; k0 += 8) {
        float4 wv = *(const float4*)(W + (size_t)(o0+wr)*CCH + k0 + wk);
        Ws[wk+0][wr] = wv.x; Ws[wk+1][wr] = wv.y;
        Ws[wk+2][wr] = wv.z; Ws[wk+3][wr] = wv.w;
        *(float4*)&Hs[hk][hc] = *(const float4*)(H + (size_t)(k0+hk)*NTOK + n0 + hc);
        __syncthreads();
        #pragma unroll
        for (int kk = 0; kk < 8; kk++) {
            float a[8], bb[8];
            #pragma unroll
            for (int i = 0; i < 8; i++) a[i]  = Ws[kk][ty*8 + i];
            #pragma unroll
            for (int j = 0; j < 8; j++) bb[j] = Hs[kk][tx*8 + j];
            #pragma unroll
            for (int i = 0; i < 8; i++)
                #pragma unroll
                for (int j = 0; j < 8; j++)
                    acc[i][j] += a[i] * bb[j];
        }
        __syncthreads();
    }

    #pragma unroll
    for (int i = 0; i < 8; i++) {
        const int o = o0 + ty*8 + i;
        const float bi = bias[o];
        #pragma unroll
        for (int j = 0; j < 8; j++) {
            const int n = n0 + tx*8 + j;
            float vv = acc[i][j] + bi;
            if (addRes) vv += X[(size_t)o*NTOK + n];
            O[(size_t)o*NTOK + n] = vv;
        }
    }
}

// ---------------- S[n][m] = scale * sum_c q[c][n]*k[c][m] ------------------
// both operands K-major with M/N contiguous -> direct smem loads
__global__ void gemm_s(const float* __restrict__ qg,
                       const float* __restrict__ kg,
                       float* __restrict__ P)
{
    const int b = blockIdx.z;
    const float* Q  = qg + (size_t)b*CCH*NTOK;
    const float* Kp = kg + (size_t)b*CCH*NTOK;
    float*       Pb = P  + (size_t)b*NTOK*NTOK;
    const int n0 = blockIdx.y * 128;
    const int m0 = blockIdx.x * 128;

    __shared__ float As[8][128];   // q tile
    __shared__ float Bs[8][128];   // k tile

    const int tid = threadIdx.x;
    const int tx = tid & 15, ty = tid >> 4;
    const int lk = tid >> 5, lc = (tid & 31) * 4;

    float acc[8][8] = {};

    for (int k0 = 0; k0 < CCH; k0 += 8) {
        *(float4*)&As[lk][lc] = *(const float4*)(Q  + (size_t)(k0+lk)*NTOK + n0 + lc);
        *(float4*)&Bs[lk][lc] = *(const float4*)(Kp + (size_t)(k0+lk)*NTOK + m0 + lc);
        __syncthreads();
        #pragma unroll
        for (int kk = 0; kk < 8; kk++) {
            float a[8], bb[8];
            #pragma unroll
            for (int i = 0; i < 8; i++) a[i]  = As[kk][ty*8 + i];
            #pragma unroll
            for (int j = 0; j < 8; j++) bb[j] = Bs[kk][tx*8 + j];
            #pragma unroll
            for (int i = 0; i < 8; i++)
                #pragma unroll
                for (int j = 0; j < 8; j++)
                    acc[i][j] += a[i] * bb[j];
        }
        __syncthreads();
    }

    #pragma unroll
    for (int i = 0; i < 8; i++) {
        const size_t n = n0 + ty*8 + i;
        #pragma unroll
        for (int j = 0; j < 8; j++)
            Pb[n*NTOK + m0 + tx*8 + j] = acc[i][j] * SCALE;
    }
}

// ---------------- row softmax in place (one block per row) -----------------
__global__ void softmax_rows(float* __restrict__ P)
{
    float* p = P + (size_t)blockIdx.x * NTOK;
    const int tid = threadIdx.x;
    float v[16];
    float mx = -3.4e38f;
    #pragma unroll
    for (int i = 0; i < 4; i++) {
        float4 t = *(const float4*)(p + i*1024 + tid*4);
        v[i*4+0] = t.x; v[i*4+1] = t.y; v[i*4+2] = t.z; v[i*4+3] = t.w;
        mx = fmaxf(mx, fmaxf(fmaxf(t.x, t.y), fmaxf(t.z, t.w)));
    }
    __shared__ float red[256];
    red[tid] = mx; __syncthreads();
    for (int off = 128; off; off >>= 1) {
        if (tid < off) red[tid] = fmaxf(red[tid], red[tid+off]);
        __syncthreads();
    }
    mx = red[0];
    __syncthreads();
    float s = 0.f;
    #pragma unroll
    for (int i = 0; i < 16; i++) { v[i] = __expf(v[i] - mx); s += v[i]; }
    red[tid] = s; __syncthreads();
    for (int off = 128; off; off >>= 1) {
        if (tid < off) red[tid] += red[tid+off];
        __syncthreads();
    }
    const float inv = 1.f / red[0];
    #pragma unroll
    for (int i = 0; i < 4; i++) {
        float4 t;
        t.x = v[i*4+0]*inv; t.y = v[i*4+1]*inv;
        t.z = v[i*4+2]*inv; t.w = v[i*4+3]*inv;
        *(float4*)(p + i*1024 + tid*4) = t;
    }
}

// ---------------- wout[b][m][n] = P[b][n][m] (tiled transpose) -------------
__global__ void transpose_p(const float* __restrict__ P, float* __restrict__ Wout)
{
    __shared__ float t[32][33];
    const int b = blockIdx.z;
    const float* Pb = P    + (size_t)b*NTOK*NTOK;
    float*       Wb = Wout + (size_t)b*NTOK*NTOK;
    const int m0 = blockIdx.x * 32;
    const int n0 = blockIdx.y * 32;
    const int x = threadIdx.x, y = threadIdx.y;   // 32 x 8
    #pragma unroll
    for (int i = 0; i < 32; i += 8)
        t[y+i][x] = Pb[(size_t)(n0+y+i)*NTOK + m0 + x];
    __syncthreads();
    #pragma unroll
    for (int i = 0; i < 32; i += 8)
        Wb[(size_t)(m0+y+i)*NTOK + n0 + x] = t[x][y+i];
}

// ---------------- hv[c][n] = sum_m v[c][m] * P[n][m]  (NT gemm) ------------
// tile 64(c) x 128(n) x 8(m); both operands K-contiguous -> transposed loads
__global__ void gemm_av(const float* __restrict__ vg,
                        const float* __restrict__ P,
                        float* __restrict__ hv)
{
    const int b = blockIdx.z;
    const float* V  = vg + (size_t)b*CCH*NTOK;
    const float* Pb = P  + (size_t)b*NTOK*NTOK;
    float*       O  = hv + (size_t)b*CCH*NTOK;
    const int c0 = blockIdx.y * 64;
    const int n0 = blockIdx.x * 128;

    __shared__ float As[8][68];    // v  transposed: [k][c]
    __shared__ float Bs[8][132];   // P  transposed: [k][n]

    const int tid = threadIdx.x;
    const int tx = tid & 15, ty = tid >> 4;    // ty: 0..15 -> 4 rows; tx: 8 cols
    const int ar = tid >> 2, ak = (tid & 3) * 2;
    const int br = tid >> 1, bk = (tid & 1) * 4;

    float acc[4][8] = {};

    for (int m0 = 0; m0 < NTOK; m0 += 8) {
        float2 av = *(const float2*)(V + (size_t)(c0+ar)*NTOK + m0 + ak);
        As[ak+0][ar] = av.x; As[ak+1][ar] = av.y;
        float4 bv = *(const float4*)(Pb + (size_t)(n0+br)*NTOK + m0 + bk);
        Bs[bk+0][br] = bv.x; Bs[bk+1][br] = bv.y;
        Bs[bk+2][br] = bv.z; Bs[bk+3][br] = bv.w;
        __syncthreads();
        #pragma unroll
        for (int kk = 0; kk < 8; kk++) {
            float a[4], bb[8];
            #pragma unroll
            for (int i = 0; i < 4; i++) a[i]  = As[kk][ty*4 + i];
            #pragma unroll
            for (int j = 0; j < 8; j++) bb[j] = Bs[kk][tx*8 + j];
            #pragma unroll
            for (int i = 0; i < 4; i++)
                #pragma unroll
                for (int j = 0; j < 8; j++)
                    acc[i][j] += a[i] * bb[j];
        }
        __syncthreads();
    }

    #pragma unroll
    for (int i = 0; i < 4; i++)
        #pragma unroll
        for (int j = 0; j < 8; j++)
            O[(size_t)(c0 + ty*4 + i)*NTOK + n0 + tx*8 + j] = acc[i][j];
}

// ---------------------------------------------------------------------------
extern "C" void kernel_launch(void* const* d_in, const int* in_sizes, int n_in,
                              void* d_out, int out_size)
{
    const float* x     = (const float*)d_in[0];
    const float* gamma = (const float*)d_in[1];
    const float* beta  = (const float*)d_in[2];
    const float* wq = (const float*)d_in[3];  const float* bq = (const float*)d_in[4];
    const float* wk = (const float*)d_in[5];  const float* bk = (const float*)d_in[6];
    const float* wv = (const float*)d_in[7];  const float* bv = (const float*)d_in[8];
    const float* wp = (const float*)d_in[9];  const float* bp = (const float*)d_in[10];

    float* out  = (float*)d_out;                              // (2,256,4096)
    float* wout = out + (size_t)BATCH*CCH*NTOK;               // (2,4096,4096)

    float *p_hn, *p_q, *p_k, *p_v, *p_hv, *p_p;
    cudaGetSymbolAddress((void**)&p_hn, g_hn);
    cudaGetSymbolAddress((void**)&p_q,  g_q);
    cudaGetSymbolAddress((void**)&p_k,  g_k);
    cudaGetSymbolAddress((void**)&p_v,  g_v);
    cudaGetSymbolAddress((void**)&p_hv, g_hv);
    cudaGetSymbolAddress((void**)&p_p,  g_p);

    // 1. GroupNorm
    gn_kernel<<<BATCH*GRP, 256>>>(x, gamma, beta, p_hn);

    // 2. q, k, v projections
    gemm_wh<<<dim3(32, 2, BATCH), 256>>>(wq, bq, p_hn, p_q, 0, nullptr);
    gemm_wh<<<dim3(32, 2, BATCH), 256>>>(wk, bk, p_hn, p_k, 0, nullptr);
    gemm_wh<<<dim3(32, 2, BATCH), 256>>>(wv, bv, p_hn, p_v, 0, nullptr);

    // 3. S = scale * q^T k
    gemm_s<<<dim3(32, 32, BATCH), 256>>>(p_q, p_k, p_p);

    // 4. softmax over m (rows of P)
    softmax_rows<<<BATCH*NTOK, 256>>>(p_p);

    // 5. returned attention = transpose(attn)
    if (out_size >= (int)((size_t)BATCH*CCH*NTOK + (size_t)BATCH*NTOK*NTOK))
        transpose_p<<<dim3(128, 128, BATCH), dim3(32, 8)>>>(p_p, wout);

    // 6. hv = v . attn^T
    gemm_av<<<dim3(32, 4, BATCH), 256>>>(p_v, p_p, p_hv);

    // 7. out = x + (wp . hv + bp)
    gemm_wh<<<dim3(32, 2, BATCH), 256>>>(wp, bp, p_hv, out, 1, x);
}

// round 4
// speedup vs baseline: 2.3494x; 2.3494x over previous
#include <cuda_runtime.h>
#include <cstdint>

#define NTOK 4096            // d*h*w = 16^3
#define CCH  256             // channels
#define BATCH 2
#define GRP  32
#define CPG  (CCH/GRP)       // 8
#define EPSV 1e-6f
#define SCALE 0.0625f        // 256^-0.5

// ---------------- scratch (device globals; no allocation allowed) ----------
__device__ float g_hn[BATCH*CCH*NTOK];
__device__ float g_q [BATCH*CCH*NTOK];
__device__ float g_k [BATCH*CCH*NTOK];
__device__ float g_v [BATCH*CCH*NTOK];
__device__ float g_hv[BATCH*CCH*NTOK];
__device__ float g_p [(size_t)BATCH*NTOK*NTOK];   // 128 MB: exp(S) unnormalized
__device__ float g_inv[BATCH*NTOK];               // 1/rowsum

// ---------------- helpers --------------------------------------------------
__device__ __forceinline__ unsigned f2tf(float f) {
    unsigned u;
    asm("cvt.rna.tf32.f32 %0, %1;" : "=r"(u) : "f"(f));
    return u;
}

__device__ __forceinline__ void mma8(float* c, const unsigned* a, const unsigned* b) {
    asm volatile(
        "mma.sync.aligned.m16n8k8.row.col.f32.tf32.tf32.f32 "
        "{%0,%1,%2,%3}, {%4,%5,%6,%7}, {%8,%9}, {%0,%1,%2,%3};\n"
        : "+f"(c[0]), "+f"(c[1]), "+f"(c[2]), "+f"(c[3])
        : "r"(a[0]), "r"(a[1]), "r"(a[2]), "r"(a[3]),
          "r"(b[0]), "r"(b[1]));
}

// ---------------- GroupNorm: one block per (b,g) ---------------------------
__global__ void gn_kernel(const float* __restrict__ x,
                          const float* __restrict__ gamma,
                          const float* __restrict__ beta,
                          float* __restrict__ hn)
{
    const int b = blockIdx.x >> 5;
    const int g = blockIdx.x & 31;
    const float* xp = x  + ((size_t)b*CCH + g*CPG) * NTOK;
    float*       hp = hn + ((size_t)b*CCH + g*CPG) * NTOK;
    const int tid = threadIdx.x;
    const int NEL = CPG * NTOK;            // 32768

    float s = 0.f, ss = 0.f;
    for (int i = tid*4; i < NEL; i += 1024) {
        float4 t = *(const float4*)(xp + i);
        s  += t.x + t.y + t.z + t.w;
        ss += t.x*t.x + t.y*t.y + t.z*t.z + t.w*t.w;
    }
    __shared__ float rs[256], rq[256];
    rs[tid] = s; rq[tid] = ss;
    __syncthreads();
    for (int off = 128; off; off >>= 1) {
        if (tid < off) { rs[tid] += rs[tid+off]; rq[tid] += rq[tid+off]; }
        __syncthreads();
    }
    const float mu   = rs[0] * (1.f/NEL);
    const float var  = rq[0] * (1.f/NEL) - mu*mu;
    const float rstd = rsqrtf(var + EPSV);

    for (int i = tid*4; i < NEL; i += 1024) {
        const int c = g*CPG + (i >> 12);   // 4096 elems per channel
        const float ga = gamma[c]*rstd, be = beta[c];
        float4 t = *(const float4*)(xp + i);
        float4 o;
        o.x = (t.x - mu)*ga + be;
        o.y = (t.y - mu)*ga + be;
        o.z = (t.z - mu)*ga + be;
        o.w = (t.w - mu)*ga + be;
        *(float4*)(hp + i) = o;
    }
}

// ---------------- C[o][n] = W[o][:] . H[:][n] (+bias)(+residual) -----------
// fp32 FFMA — kept full precision so tf32 error doesn't compound through q/k/v
__global__ void gemm_wh(const float* __restrict__ W,
                        const float* __restrict__ bias,
                        const float* __restrict__ Hbase,
                        float* __restrict__ Obase,
                        int addRes,
                        const float* __restrict__ Xbase)
{
    const int b  = blockIdx.z;
    const float* H = Hbase + (size_t)b*CCH*NTOK;
    float*       O = Obase + (size_t)b*CCH*NTOK;
    const float* X = addRes ? (Xbase + (size_t)b*CCH*NTOK) : nullptr;
    const int o0 = blockIdx.y * 128;
    const int n0 = blockIdx.x * 128;

    __shared__ float Ws[8][132];
    __shared__ float Hs[8][128];

    const int tid = threadIdx.x;
    const int tx = tid & 15, ty = tid >> 4;
    const int wr = tid >> 1, wk = (tid & 1) * 4;
    const int hk = tid >> 5, hc = (tid & 31) * 4;

    float acc[8][8] = {};

    for (int k0 = 0; k0 < CCH; k0 += 8) {
        float4 wv = *(const float4*)(W + (size_t)(o0+wr)*CCH + k0 + wk);
        Ws[wk+0][wr] = wv.x; Ws[wk+1][wr] = wv.y;
        Ws[wk+2][wr] = wv.z; Ws[wk+3][wr] = wv.w;
        *(float4*)&Hs[hk][hc] = *(const float4*)(H + (size_t)(k0+hk)*NTOK + n0 + hc);
        __syncthreads();
        #pragma unroll
        for (int kk = 0; kk < 8; kk++) {
            float a[8], bb[8];
            #pragma unroll
            for (int i = 0; i < 8; i++) a[i]  = Ws[kk][ty*8 + i];
            #pragma unroll
            for (int j = 0; j < 8; j++) bb[j] = Hs[kk][tx*8 + j];
            #pragma unroll
            for (int i = 0; i < 8; i++)
                #pragma unroll
                for (int j = 0; j < 8; j++)
                    acc[i][j] += a[i] * bb[j];
        }
        __syncthreads();
    }

    #pragma unroll
    for (int i = 0; i < 8; i++) {
        const int o = o0 + ty*8 + i;
        const float bi = bias[o];
        #pragma unroll
        for (int j = 0; j < 8; j++) {
            const int n = n0 + tx*8 + j;
            float vv = acc[i][j] + bi;
            if (addRes) vv += X[(size_t)o*NTOK + n];
            O[(size_t)o*NTOK + n] = vv;
        }
    }
}

// ---------------- E[n][m] = exp(scale * sum_c q[c][n]*k[c][m]) -------------
// tf32 mma.sync; block 128(n) x 128(m) x k16; 8 warps, warp tile 64x32
__global__ void __launch_bounds__(256, 2)
mm_s_tf32(const float* __restrict__ qg,
          const float* __restrict__ kg,
          float* __restrict__ E)
{
    const int b = blockIdx.z;
    const float* Q  = qg + (size_t)b*CCH*NTOK;
    const float* Kp = kg + (size_t)b*CCH*NTOK;
    float*       Eb = E  + (size_t)b*NTOK*NTOK;
    const int n0 = blockIdx.y * 128;
    const int m0 = blockIdx.x * 128;

    __shared__ unsigned As[16][136];   // [k][n]  (q)
    __shared__ unsigned Bs[16][136];   // [k][m]  (k)

    const int tid  = threadIdx.x;
    const int lane = tid & 31;
    const int wid  = tid >> 5;
    const int wr   = (wid & 1) * 64;   // n offset
    const int wc   = (wid >> 1) * 32;  // m offset
    const int lq   = lane >> 2;        // 0..7
    const int lr   = lane & 3;         // 0..3

    float acc[4][4][4] = {};           // [mt(n)][nt(m)][4]

    for (int k0 = 0; k0 < CCH; k0 += 16) {
        #pragma unroll
        for (int s = 0; s < 2; s++) {
            int idx = tid + s*256;
            int kc = idx >> 5, c4 = (idx & 31) * 4;
            float4 qa = *(const float4*)(Q  + (size_t)(k0+kc)*NTOK + n0 + c4);
            float4 ka = *(const float4*)(Kp + (size_t)(k0+kc)*NTOK + m0 + c4);
            uint4 qu; qu.x = f2tf(qa.x); qu.y = f2tf(qa.y); qu.z = f2tf(qa.z); qu.w = f2tf(qa.w);
            uint4 ku; ku.x = f2tf(ka.x); ku.y = f2tf(ka.y); ku.z = f2tf(ka.z); ku.w = f2tf(ka.w);
            *(uint4*)&As[kc][c4] = qu;
            *(uint4*)&Bs[kc][c4] = ku;
        }
        __syncthreads();
        #pragma unroll
        for (int kk = 0; kk < 16; kk += 8) {
            unsigned bfr[4][2];
            #pragma unroll
            for (int nt = 0; nt < 4; nt++) {
                int col = wc + nt*8 + lq;
                bfr[nt][0] = Bs[kk + lr    ][col];
                bfr[nt][1] = Bs[kk + 4 + lr][col];
            }
            #pragma unroll
            for (int mt = 0; mt < 4; mt++) {
                unsigned afr[4];
                int rb = wr + mt*16 + lq;
                afr[0] = As[kk + lr    ][rb];
                afr[1] = As[kk + lr    ][rb + 8];
                afr[2] = As[kk + 4 + lr][rb];
                afr[3] = As[kk + 4 + lr][rb + 8];
                #pragma unroll
                for (int nt = 0; nt < 4; nt++)
                    mma8(acc[mt][nt], afr, bfr[nt]);
            }
        }
        __syncthreads();
    }

    // epilogue: E = exp(acc * SCALE)   (no max-subtract: |logit| <~ 6)
    #pragma unroll
    for (int mt = 0; mt < 4; mt++) {
        const size_t n = n0 + wr + mt*16 + lq;
        #pragma unroll
        for (int nt = 0; nt < 4; nt++) {
            const int m = m0 + wc + nt*8 + 2*lr;
            float2 v0, v1;
            v0.x = __expf(acc[mt][nt][0] * SCALE);
            v0.y = __expf(acc[mt][nt][1] * SCALE);
            v1.x = __expf(acc[mt][nt][2] * SCALE);
            v1.y = __expf(acc[mt][nt][3] * SCALE);
            *(float2*)(Eb + n*NTOK + m)        = v0;
            *(float2*)(Eb + (n+8)*NTOK + m)    = v1;
        }
    }
}

// ---------------- inv[n] = 1 / sum_m E[n][m]  (one warp per row) -----------
__global__ void rowsum_kernel(const float* __restrict__ E, float* __restrict__ inv)
{
    const int b    = blockIdx.y;
    const int row  = blockIdx.x * 8 + (threadIdx.x >> 5);
    const int lane = threadIdx.x & 31;
    const float* p = E + (size_t)b*NTOK*NTOK + (size_t)row*NTOK;
    float s = 0.f;
    for (int i = lane*4; i < NTOK; i += 128) {
        float4 t = *(const float4*)(p + i);
        s += t.x + t.y + t.z + t.w;
    }
    #pragma unroll
    for (int o = 16; o; o >>= 1) s += __shfl_xor_sync(0xffffffffu, s, o);
    if (lane == 0) inv[b*NTOK + row] = 1.f / s;
}

// ---------------- wout[b][m][n] = E[b][n][m] * inv[b][n] -------------------
__global__ void transpose_scale(const float* __restrict__ E,
                                const float* __restrict__ inv,
                                float* __restrict__ Wout)
{
    __shared__ float t[32][33];
    __shared__ float is[32];
    const int b = blockIdx.z;
    const float* Eb = E    + (size_t)b*NTOK*NTOK;
    float*       Wb = Wout + (size_t)b*NTOK*NTOK;
    const int m0 = blockIdx.x * 32;
    const int n0 = blockIdx.y * 32;
    const int x = threadIdx.x, y = threadIdx.y;   // 32 x 8
    if (y == 0) is[x] = inv[b*NTOK + n0 + x];
    #pragma unroll
    for (int i = 0; i < 32; i += 8)
        t[y+i][x] = Eb[(size_t)(n0+y+i)*NTOK + m0 + x];
    __syncthreads();
    #pragma unroll
    for (int i = 0; i < 32; i += 8)
        Wb[(size_t)(m0+y+i)*NTOK + n0 + x] = t[x][y+i] * is[x];
}

// ---------------- hv[c][n] = inv[n] * sum_m V[c][m] * E[n][m] --------------
// tf32 mma; block 64(c) x 128(n), k16; 8 warps, warp tile 32x32
__global__ void __launch_bounds__(256)
mm_av_tf32(const float* __restrict__ vg,
           const float* __restrict__ E,
           const float* __restrict__ inv,
           float* __restrict__ hv)
{
    const int b = blockIdx.z;
    const float* V  = vg + (size_t)b*CCH*NTOK;
    const float* Eb = E  + (size_t)b*NTOK*NTOK;
    float*       O  = hv + (size_t)b*CCH*NTOK;
    const int c0 = blockIdx.y * 64;
    const int n0 = blockIdx.x * 128;

    __shared__ unsigned As[64][20];    // [c][k]  (V, k-contig)
    __shared__ unsigned Bs[128][20];   // [n][k]  (E, k-contig)
    __shared__ float    invs[128];

    const int tid  = threadIdx.x;
    const int lane = tid & 31;
    const int wid  = tid >> 5;
    const int wr   = (wid & 1) * 32;   // c offset
    const int wc   = (wid >> 1) * 32;  // n offset
    const int lq   = lane >> 2;
    const int lr   = lane & 3;

    if (tid < 128) invs[tid] = inv[b*NTOK + n0 + tid];

    float acc[2][4][4] = {};           // [mt(c)][nt(n)][4]

    for (int m0i = 0; m0i < NTOK; m0i += 16) {
        {   // stage V: 64x16
            int c = tid >> 2, k4 = (tid & 3) * 4;
            float4 va = *(const float4*)(V + (size_t)(c0+c)*NTOK + m0i + k4);
            uint4 u; u.x = f2tf(va.x); u.y = f2tf(va.y); u.z = f2tf(va.z); u.w = f2tf(va.w);
            *(uint4*)&As[c][k4] = u;
        }
        #pragma unroll
        for (int s = 0; s < 2; s++) {   // stage E: 128x16
            int idx = tid + s*256;
            int n = idx >> 2, k4 = (idx & 3) * 4;
            float4 ea = *(const float4*)(Eb + (size_t)(n0+n)*NTOK + m0i + k4);
            uint4 u; u.x = f2tf(ea.x); u.y = f2tf(ea.y); u.z = f2tf(ea.z); u.w = f2tf(ea.w);
            *(uint4*)&Bs[n][k4] = u;
        }
        __syncthreads();
        #pragma unroll
        for (int kk = 0; kk < 16; kk += 8) {
            unsigned bfr[4][2];
            #pragma unroll
            for (int nt = 0; nt < 4; nt++) {
                int col = wc + nt*8 + lq;
                bfr[nt][0] = Bs[col][kk + lr];
                bfr[nt][1] = Bs[col][kk + 4 + lr];
            }
            #pragma unroll
            for (int mt = 0; mt < 2; mt++) {
                unsigned afr[4];
                int rb = wr + mt*16 + lq;
                afr[0] = As[rb    ][kk + lr];
                afr[1] = As[rb + 8][kk + lr];
                afr[2] = As[rb    ][kk + 4 + lr];
                afr[3] = As[rb + 8][kk + 4 + lr];
                #pragma unroll
                for (int nt = 0; nt < 4; nt++)
                    mma8(acc[mt][nt], afr, bfr[nt]);
            }
        }
        __syncthreads();
    }

    #pragma unroll
    for (int mt = 0; mt < 2; mt++) {
        const int row = wr + mt*16 + lq;
        #pragma unroll
        for (int nt = 0; nt < 4; nt++) {
            const int nl = wc + nt*8 + 2*lr;
            const float i0 = invs[nl], i1 = invs[nl+1];
            float2 v0, v1;
            v0.x = acc[mt][nt][0] * i0;  v0.y = acc[mt][nt][1] * i1;
            v1.x = acc[mt][nt][2] * i0;  v1.y = acc[mt][nt][3] * i1;
            *(float2*)(O + (size_t)(c0+row  )*NTOK + n0 + nl) = v0;
            *(float2*)(O + (size_t)(c0+row+8)*NTOK + n0 + nl) = v1;
        }
    }
}

// ---------------------------------------------------------------------------
extern "C" void kernel_launch(void* const* d_in, const int* in_sizes, int n_in,
                              void* d_out, int out_size)
{
    const float* x     = (const float*)d_in[0];
    const float* gamma = (const float*)d_in[1];
    const float* beta  = (const float*)d_in[2];
    const float* wq = (const float*)d_in[3];  const float* bq = (const float*)d_in[4];
    const float* wk = (const float*)d_in[5];  const float* bk = (const float*)d_in[6];
    const float* wv = (const float*)d_in[7];  const float* bv = (const float*)d_in[8];
    const float* wp = (const float*)d_in[9];  const float* bp = (const float*)d_in[10];

    float* out  = (float*)d_out;                              // (2,256,4096)
    float* wout = out + (size_t)BATCH*CCH*NTOK;               // (2,4096,4096)

    float *p_hn, *p_q, *p_k, *p_v, *p_hv, *p_p, *p_inv;
    cudaGetSymbolAddress((void**)&p_hn,  g_hn);
    cudaGetSymbolAddress((void**)&p_q,   g_q);
    cudaGetSymbolAddress((void**)&p_k,   g_k);
    cudaGetSymbolAddress((void**)&p_v,   g_v);
    cudaGetSymbolAddress((void**)&p_hv,  g_hv);
    cudaGetSymbolAddress((void**)&p_p,   g_p);
    cudaGetSymbolAddress((void**)&p_inv, g_inv);

    // 1. GroupNorm
    gn_kernel<<<BATCH*GRP, 256>>>(x, gamma, beta, p_hn);

    // 2. q, k, v projections (fp32)
    gemm_wh<<<dim3(32, 2, BATCH), 256>>>(wq, bq, p_hn, p_q, 0, nullptr);
    gemm_wh<<<dim3(32, 2, BATCH), 256>>>(wk, bk, p_hn, p_k, 0, nullptr);
    gemm_wh<<<dim3(32, 2, BATCH), 256>>>(wv, bv, p_hn, p_v, 0, nullptr);

    // 3. E = exp(scale * q^T k)   (tf32 tensor cores)
    mm_s_tf32<<<dim3(32, 32, BATCH), 256>>>(p_q, p_k, p_p);

    // 4. row sums -> inv
    rowsum_kernel<<<dim3(512, BATCH), 256>>>(p_p, p_inv);

    // 5. returned attention = normalize + transpose
    if (out_size >= (int)((size_t)BATCH*CCH*NTOK + (size_t)BATCH*NTOK*NTOK))
        transpose_scale<<<dim3(128, 128, BATCH), dim3(32, 8)>>>(p_p, p_inv, wout);

    // 6. hv = (v . E^T) * inv    (tf32 tensor cores)
    mm_av_tf32<<<dim3(32, 4, BATCH), 256>>>(p_v, p_p, p_inv, p_hv);

    // 7. out = x + (wp . hv + bp)  (fp32)
    gemm_wh<<<dim3(32, 2, BATCH), 256>>>(wp, bp, p_hv, out, 1, x);
}

// round 7
// speedup vs baseline: 2.6963x; 1.1476x over previous
#include <cuda_runtime.h>
#include <cstdint>

#define NTOK 4096            // d*h*w = 16^3
#define CCH  256             // channels
#define BATCH 2
#define GRP  32
#define CPG  (CCH/GRP)       // 8
#define EPSV 1e-6f
#define SCALE 0.0625f        // 256^-0.5

// ---------------- scratch (device globals; no allocation allowed) ----------
__device__ float g_hn[BATCH*CCH*NTOK];
__device__ float g_q [BATCH*CCH*NTOK];
__device__ float g_k [BATCH*CCH*NTOK];
__device__ float g_v [BATCH*CCH*NTOK];
__device__ float g_hv[BATCH*CCH*NTOK];
__device__ float g_p [(size_t)BATCH*NTOK*NTOK];   // 128 MB: exp(S) unnormalized
__device__ float g_sum[BATCH*NTOK];               // row sums (atomic)
__device__ float g_inv[BATCH*NTOK];               // 1/rowsum
__device__ float g_stats[BATCH*GRP*2];            // groupnorm sum / sumsq

// ---------------- helpers --------------------------------------------------
__device__ __forceinline__ unsigned f2tf(float f) {
    unsigned u;
    asm("cvt.rna.tf32.f32 %0, %1;" : "=r"(u) : "f"(f));
    return u;
}

__device__ __forceinline__ void mma8(float* c, const unsigned* a, const unsigned* b) {
    asm volatile(
        "mma.sync.aligned.m16n8k8.row.col.f32.tf32.tf32.f32 "
        "{%0,%1,%2,%3}, {%4,%5,%6,%7}, {%8,%9}, {%0,%1,%2,%3};\n"
        : "+f"(c[0]), "+f"(c[1]), "+f"(c[2]), "+f"(c[3])
        : "r"(a[0]), "r"(a[1]), "r"(a[2]), "r"(a[3]),
          "r"(b[0]), "r"(b[1]));
}

// ---------------- zero accumulators ---------------------------------------
__global__ void zero_kernel()
{
    const int i = blockIdx.x * 256 + threadIdx.x;
    if (i < BATCH*NTOK) g_sum[i] = 0.f;
    if (i < BATCH*GRP*2) g_stats[i] = 0.f;
}

// ---------------- GroupNorm pass 1: partial stats (8 chunks per group) -----
// FIX vs round 5: loop over ALL 4096 elements of the chunk (4 float4 / thread)
__global__ void gn_stats(const float* __restrict__ x)
{
    const int gidx  = blockIdx.x >> 3;            // b*32+g
    const int chunk = blockIdx.x & 7;
    const float* xp = x + (size_t)gidx*CPG*NTOK + chunk*NTOK;
    const int tid = threadIdx.x;

    float s = 0.f, ss = 0.f;
    #pragma unroll
    for (int i = tid*4; i < NTOK; i += 1024) {
        float4 t = *(const float4*)(xp + i);
        s  += t.x + t.y + t.z + t.w;
        ss += t.x*t.x + t.y*t.y + t.z*t.z + t.w*t.w;
    }
    __shared__ float rs[256], rq[256];
    rs[tid] = s; rq[tid] = ss;
    __syncthreads();
    for (int off = 128; off; off >>= 1) {
        if (tid < off) { rs[tid] += rs[tid+off]; rq[tid] += rq[tid+off]; }
        __syncthreads();
    }
    if (tid == 0) {
        atomicAdd(&g_stats[2*gidx],   rs[0]);
        atomicAdd(&g_stats[2*gidx+1], rq[0]);
    }
}

// ---------------- GroupNorm pass 2: one channel per block ------------------
__global__ void gn_apply(const float* __restrict__ x,
                         const float* __restrict__ gamma,
                         const float* __restrict__ beta,
                         float* __restrict__ hn)
{
    const int c    = blockIdx.x & 255;
    const int gidx = (blockIdx.x >> 8) * GRP + (c >> 3);
    const float mu   = g_stats[2*gidx]   * (1.f/32768.f);
    const float var  = g_stats[2*gidx+1] * (1.f/32768.f) - mu*mu;
    const float rstd = rsqrtf(var + EPSV);
    const float ga = gamma[c]*rstd, be = beta[c];

    const size_t base = (size_t)blockIdx.x * NTOK;
    const int i = threadIdx.x * 4;
    #pragma unroll
    for (int s = 0; s < 4; s++) {
        float4 t = *(const float4*)(x + base + i + s*1024);
        float4 o;
        o.x = (t.x - mu)*ga + be;
        o.y = (t.y - mu)*ga + be;
        o.z = (t.z - mu)*ga + be;
        o.w = (t.w - mu)*ga + be;
        *(float4*)(hn + base + i + s*1024) = o;
    }
}

// ---------------- C[o][n] = W.H (+bias)(+res), 3xTF32 split MMA ------------
// error-compensated tf32: C ~= Ah.Bh + Ah.Bl + Al.Bh  (~fp32 accuracy)
// block 128(o) x 128(n) x k16; 8 warps, warp tile 64x32
__global__ void __launch_bounds__(256)
mm_wh_tf32(const float* __restrict__ W,
           const float* __restrict__ bias,
           const float* __restrict__ Hbase,
           float* __restrict__ Obase,
           int addRes,
           const float* __restrict__ Xbase)
{
    const int b  = blockIdx.z;
    const float* H = Hbase + (size_t)b*CCH*NTOK;
    float*       O = Obase + (size_t)b*CCH*NTOK;
    const float* X = addRes ? (Xbase + (size_t)b*CCH*NTOK) : nullptr;
    const int o0 = blockIdx.y * 128;
    const int n0 = blockIdx.x * 128;

    __shared__ unsigned Ah[16][136], Al[16][136];   // [k][o]  W split
    __shared__ unsigned Bh[16][136], Bl[16][136];   // [k][n]  H split

    const int tid  = threadIdx.x;
    const int lane = tid & 31;
    const int wid  = tid >> 5;
    const int wr   = (wid & 1) * 64;   // o offset
    const int wc   = (wid >> 1) * 32;  // n offset
    const int lq   = lane >> 2;
    const int lr   = lane & 3;

    const int wo = tid >> 1, wk0 = (tid & 1) * 8;   // W load: 2 float4 along k
    float acc[4][4][4] = {};

    for (int k0 = 0; k0 < CCH; k0 += 16) {
        #pragma unroll
        for (int s = 0; s < 2; s++) {
            float4 wv = *(const float4*)(W + (size_t)(o0+wo)*CCH + k0 + wk0 + s*4);
            float f[4] = {wv.x, wv.y, wv.z, wv.w};
            #pragma unroll
            for (int j = 0; j < 4; j++) {
                unsigned h = f2tf(f[j]);
                Ah[wk0+s*4+j][wo] = h;
                Al[wk0+s*4+j][wo] = f2tf(f[j] - __uint_as_float(h));
            }
        }
        #pragma unroll
        for (int s = 0; s < 2; s++) {
            int idx = tid + s*256;
            int kc = idx >> 5, c4 = (idx & 31) * 4;
            float4 ha = *(const float4*)(H + (size_t)(k0+kc)*NTOK + n0 + c4);
            float f[4] = {ha.x, ha.y, ha.z, ha.w};
            uint4 uh, ul;
            uh.x = f2tf(f[0]); ul.x = f2tf(f[0] - __uint_as_float(uh.x));
            uh.y = f2tf(f[1]); ul.y = f2tf(f[1] - __uint_as_float(uh.y));
            uh.z = f2tf(f[2]); ul.z = f2tf(f[2] - __uint_as_float(uh.z));
            uh.w = f2tf(f[3]); ul.w = f2tf(f[3] - __uint_as_float(uh.w));
            *(uint4*)&Bh[kc][c4] = uh;
            *(uint4*)&Bl[kc][c4] = ul;
        }
        __syncthreads();
        #pragma unroll
        for (int kk = 0; kk < 16; kk += 8) {
            unsigned bh[4][2], bl[4][2];
            #pragma unroll
            for (int nt = 0; nt < 4; nt++) {
                int col = wc + nt*8 + lq;
                bh[nt][0] = Bh[kk + lr    ][col];
                bh[nt][1] = Bh[kk + 4 + lr][col];
                bl[nt][0] = Bl[kk + lr    ][col];
                bl[nt][1] = Bl[kk + 4 + lr][col];
            }
            #pragma unroll
            for (int mt = 0; mt < 4; mt++) {
                unsigned ah[4], al[4];
                int rb = wr + mt*16 + lq;
                ah[0] = Ah[kk + lr    ][rb];   ah[1] = Ah[kk + lr    ][rb + 8];
                ah[2] = Ah[kk + 4 + lr][rb];   ah[3] = Ah[kk + 4 + lr][rb + 8];
                al[0] = Al[kk + lr    ][rb];   al[1] = Al[kk + lr    ][rb + 8];
                al[2] = Al[kk + 4 + lr][rb];   al[3] = Al[kk + 4 + lr][rb + 8];
                #pragma unroll
                for (int nt = 0; nt < 4; nt++) {
                    mma8(acc[mt][nt], ah, bh[nt]);
                    mma8(acc[mt][nt], ah, bl[nt]);
                    mma8(acc[mt][nt], al, bh[nt]);
                }
            }
        }
        __syncthreads();
    }

    #pragma unroll
    for (int mt = 0; mt < 4; mt++) {
        const int o = o0 + wr + mt*16 + lq;
        const float bi0 = bias[o], bi1 = bias[o+8];
        #pragma unroll
        for (int nt = 0; nt < 4; nt++) {
            const int n = n0 + wc + nt*8 + 2*lr;
            float2 v0, v1;
            v0.x = acc[mt][nt][0] + bi0;  v0.y = acc[mt][nt][1] + bi0;
            v1.x = acc[mt][nt][2] + bi1;  v1.y = acc[mt][nt][3] + bi1;
            if (addRes) {
                float2 x0 = *(const float2*)(X + (size_t)o*NTOK + n);
                float2 x1 = *(const float2*)(X + (size_t)(o+8)*NTOK + n);
                v0.x += x0.x; v0.y += x0.y;
                v1.x += x1.x; v1.y += x1.y;
            }
            *(float2*)(O + (size_t)o*NTOK + n)     = v0;
            *(float2*)(O + (size_t)(o+8)*NTOK + n) = v1;
        }
    }
}

// ---------------- E[n][m] = exp(scale * q^T k); fused row-sum atomics ------
__global__ void __launch_bounds__(256, 2)
mm_s_tf32(const float* __restrict__ qg,
          const float* __restrict__ kg,
          float* __restrict__ E)
{
    const int b = blockIdx.z;
    const float* Q  = qg + (size_t)b*CCH*NTOK;
    const float* Kp = kg + (size_t)b*CCH*NTOK;
    float*       Eb = E  + (size_t)b*NTOK*NTOK;
    const int n0 = blockIdx.y * 128;
    const int m0 = blockIdx.x * 128;

    __shared__ unsigned As[16][136];   // [k][n]  (q)
    __shared__ unsigned Bs[16][136];   // [k][m]  (k)

    const int tid  = threadIdx.x;
    const int lane = tid & 31;
    const int wid  = tid >> 5;
    const int wr   = (wid & 1) * 64;   // n offset
    const int wc   = (wid >> 1) * 32;  // m offset
    const int lq   = lane >> 2;        // 0..7
    const int lr   = lane & 3;         // 0..3

    float acc[4][4][4] = {};

    for (int k0 = 0; k0 < CCH; k0 += 16) {
        #pragma unroll
        for (int s = 0; s < 2; s++) {
            int idx = tid + s*256;
            int kc = idx >> 5, c4 = (idx & 31) * 4;
            float4 qa = *(const float4*)(Q  + (size_t)(k0+kc)*NTOK + n0 + c4);
            float4 ka = *(const float4*)(Kp + (size_t)(k0+kc)*NTOK + m0 + c4);
            uint4 qu; qu.x = f2tf(qa.x); qu.y = f2tf(qa.y); qu.z = f2tf(qa.z); qu.w = f2tf(qa.w);
            uint4 ku; ku.x = f2tf(ka.x); ku.y = f2tf(ka.y); ku.z = f2tf(ka.z); ku.w = f2tf(ka.w);
            *(uint4*)&As[kc][c4] = qu;
            *(uint4*)&Bs[kc][c4] = ku;
        }
        __syncthreads();
        #pragma unroll
        for (int kk = 0; kk < 16; kk += 8) {
            unsigned bfr[4][2];
            #pragma unroll
            for (int nt = 0; nt < 4; nt++) {
                int col = wc + nt*8 + lq;
                bfr[nt][0] = Bs[kk + lr    ][col];
                bfr[nt][1] = Bs[kk + 4 + lr][col];
            }
            #pragma unroll
            for (int mt = 0; mt < 4; mt++) {
                unsigned afr[4];
                int rb = wr + mt*16 + lq;
                afr[0] = As[kk + lr    ][rb];
                afr[1] = As[kk + lr    ][rb + 8];
                afr[2] = As[kk + 4 + lr][rb];
                afr[3] = As[kk + 4 + lr][rb + 8];
                #pragma unroll
                for (int nt = 0; nt < 4; nt++)
                    mma8(acc[mt][nt], afr, bfr[nt]);
            }
        }
        __syncthreads();
    }

    // epilogue: E = exp(acc*SCALE), accumulate row sums, atomic into g_sum
    #pragma unroll
    for (int mt = 0; mt < 4; mt++) {
        const size_t n = n0 + wr + mt*16 + lq;
        float rs0 = 0.f, rs1 = 0.f;
        #pragma unroll
        for (int nt = 0; nt < 4; nt++) {
            const int m = m0 + wc + nt*8 + 2*lr;
            float2 v0, v1;
            v0.x = __expf(acc[mt][nt][0] * SCALE);
            v0.y = __expf(acc[mt][nt][1] * SCALE);
            v1.x = __expf(acc[mt][nt][2] * SCALE);
            v1.y = __expf(acc[mt][nt][3] * SCALE);
            rs0 += v0.x + v0.y;
            rs1 += v1.x + v1.y;
            *(float2*)(Eb + n*NTOK + m)     = v0;
            *(float2*)(Eb + (n+8)*NTOK + m) = v1;
        }
        rs0 += __shfl_xor_sync(0xffffffffu, rs0, 1);
        rs0 += __shfl_xor_sync(0xffffffffu, rs0, 2);
        rs1 += __shfl_xor_sync(0xffffffffu, rs1, 1);
        rs1 += __shfl_xor_sync(0xffffffffu, rs1, 2);
        if (lr == 0) {
            atomicAdd(&g_sum[b*NTOK + n],     rs0);
            atomicAdd(&g_sum[b*NTOK + n + 8], rs1);
        }
    }
}

// ---------------- inv[i] = 1/sum[i] ----------------------------------------
__global__ void inv_kernel()
{
    const int i = blockIdx.x * 256 + threadIdx.x;
    if (i < BATCH*NTOK) g_inv[i] = 1.f / g_sum[i];
}

// ---------------- wout[b][m][n] = E[b][n][m] * inv[b][n] -------------------
__global__ void transpose_scale(const float* __restrict__ E,
                                const float* __restrict__ inv,
                                float* __restrict__ Wout)
{
    __shared__ float t[32][33];
    __shared__ float is[32];
    const int b = blockIdx.z;
    const float* Eb = E    + (size_t)b*NTOK*NTOK;
    float*       Wb = Wout + (size_t)b*NTOK*NTOK;
    const int m0 = blockIdx.x * 32;
    const int n0 = blockIdx.y * 32;
    const int x = threadIdx.x, y = threadIdx.y;   // 32 x 8
    if (y == 0) is[x] = inv[b*NTOK + n0 + x];
    #pragma unroll
    for (int i = 0; i < 32; i += 8)
        t[y+i][x] = Eb[(size_t)(n0+y+i)*NTOK + m0 + x];
    __syncthreads();
    #pragma unroll
    for (int i = 0; i < 32; i += 8)
        Wb[(size_t)(m0+y+i)*NTOK + n0 + x] = t[x][y+i] * is[x];
}

// ---------------- hv[c][n] = inv[n] * sum_m V[c][m] * E[n][m] --------------
__global__ void __launch_bounds__(256)
mm_av_tf32(const float* __restrict__ vg,
           const float* __restrict__ E,
           const float* __restrict__ inv,
           float* __restrict__ hv)
{
    const int b = blockIdx.z;
    const float* V  = vg + (size_t)b*CCH*NTOK;
    const float* Eb = E  + (size_t)b*NTOK*NTOK;
    float*       O  = hv + (size_t)b*CCH*NTOK;
    const int c0 = blockIdx.y * 64;
    const int n0 = blockIdx.x * 128;

    __shared__ unsigned As[64][20];    // [c][k]  (V, k-contig)
    __shared__ unsigned Bs[128][20];   // [n][k]  (E, k-contig)
    __shared__ float    invs[128];

    const int tid  = threadIdx.x;
    const int lane = tid & 31;
    const int wid  = tid >> 5;
    const int wr   = (wid & 1) * 32;   // c offset
    const int wc   = (wid >> 1) * 32;  // n offset
    const int lq   = lane >> 2;
    const int lr   = lane & 3;

    if (tid < 128) invs[tid] = inv[b*NTOK + n0 + tid];

    float acc[2][4][4] = {};

    for (int m0i = 0; m0i < NTOK; m0i += 16) {
        {   // stage V: 64x16
            int c = tid >> 2, k4 = (tid & 3) * 4;
            float4 va = *(const float4*)(V + (size_t)(c0+c)*NTOK + m0i + k4);
            uint4 u; u.x = f2tf(va.x); u.y = f2tf(va.y); u.z = f2tf(va.z); u.w = f2tf(va.w);
            *(uint4*)&As[c][k4] = u;
        }
        #pragma unroll
        for (int s = 0; s < 2; s++) {   // stage E: 128x16
            int idx = tid + s*256;
            int n = idx >> 2, k4 = (idx & 3) * 4;
            float4 ea = *(const float4*)(Eb + (size_t)(n0+n)*NTOK + m0i + k4);
            uint4 u; u.x = f2tf(ea.x); u.y = f2tf(ea.y); u.z = f2tf(ea.z); u.w = f2tf(ea.w);
            *(uint4*)&Bs[n][k4] = u;
        }
        __syncthreads();
        #pragma unroll
        for (int kk = 0; kk < 16; kk += 8) {
            unsigned bfr[4][2];
            #pragma unroll
            for (int nt = 0; nt < 4; nt++) {
                int col = wc + nt*8 + lq;
                bfr[nt][0] = Bs[col][kk + lr];
                bfr[nt][1] = Bs[col][kk + 4 + lr];
            }
            #pragma unroll
            for (int mt = 0; mt < 2; mt++) {
                unsigned afr[4];
                int rb = wr + mt*16 + lq;
                afr[0] = As[rb    ][kk + lr];
                afr[1] = As[rb + 8][kk + lr];
                afr[2] = As[rb    ][kk + 4 + lr];
                afr[3] = As[rb + 8][kk + 4 + lr];
                #pragma unroll
                for (int nt = 0; nt < 4; nt++)
                    mma8(acc[mt][nt], afr, bfr[nt]);
            }
        }
        __syncthreads();
    }

    #pragma unroll
    for (int mt = 0; mt < 2; mt++) {
        const int row = wr + mt*16 + lq;
        #pragma unroll
        for (int nt = 0; nt < 4; nt++) {
            const int nl = wc + nt*8 + 2*lr;
            const float i0 = invs[nl], i1 = invs[nl+1];
            float2 v0, v1;
            v0.x = acc[mt][nt][0] * i0;  v0.y = acc[mt][nt][1] * i1;
            v1.x = acc[mt][nt][2] * i0;  v1.y = acc[mt][nt][3] * i1;
            *(float2*)(O + (size_t)(c0+row  )*NTOK + n0 + nl) = v0;
            *(float2*)(O + (size_t)(c0+row+8)*NTOK + n0 + nl) = v1;
        }
    }
}

// ---------------------------------------------------------------------------
extern "C" void kernel_launch(void* const* d_in, const int* in_sizes, int n_in,
                              void* d_out, int out_size)
{
    const float* x     = (const float*)d_in[0];
    const float* gamma = (const float*)d_in[1];
    const float* beta  = (const float*)d_in[2];
    const float* wq = (const float*)d_in[3];  const float* bq = (const float*)d_in[4];
    const float* wk = (const float*)d_in[5];  const float* bk = (const float*)d_in[6];
    const float* wv = (const float*)d_in[7];  const float* bv = (const float*)d_in[8];
    const float* wp = (const float*)d_in[9];  const float* bp = (const float*)d_in[10];

    float* out  = (float*)d_out;                              // (2,256,4096)
    float* wout = out + (size_t)BATCH*CCH*NTOK;               // (2,4096,4096)

    float *p_hn, *p_q, *p_k, *p_v, *p_hv, *p_p, *p_inv;
    cudaGetSymbolAddress((void**)&p_hn,  g_hn);
    cudaGetSymbolAddress((void**)&p_q,   g_q);
    cudaGetSymbolAddress((void**)&p_k,   g_k);
    cudaGetSymbolAddress((void**)&p_v,   g_v);
    cudaGetSymbolAddress((void**)&p_hv,  g_hv);
    cudaGetSymbolAddress((void**)&p_p,   g_p);
    cudaGetSymbolAddress((void**)&p_inv, g_inv);

    // 0. zero row-sum and stats accumulators
    zero_kernel<<<33, 256>>>();

    // 1. GroupNorm (two-pass, chip-filling)
    gn_stats<<<BATCH*GRP*8, 256>>>(x);
    gn_apply<<<BATCH*CCH, 256>>>(x, gamma, beta, p_hn);

    // 2. q, k, v projections (3xTF32 split ~ fp32 accuracy)
    mm_wh_tf32<<<dim3(32, 2, BATCH), 256>>>(wq, bq, p_hn, p_q, 0, nullptr);
    mm_wh_tf32<<<dim3(32, 2, BATCH), 256>>>(wk, bk, p_hn, p_k, 0, nullptr);
    mm_wh_tf32<<<dim3(32, 2, BATCH), 256>>>(wv, bv, p_hn, p_v, 0, nullptr);

    // 3. E = exp(scale * q^T k) with fused row sums
    mm_s_tf32<<<dim3(32, 32, BATCH), 256>>>(p_q, p_k, p_p);

    // 4. reciprocal of row sums
    inv_kernel<<<32, 256>>>();

    // 5. returned attention = normalize + transpose
    if (out_size >= (int)((size_t)BATCH*CCH*NTOK + (size_t)BATCH*NTOK*NTOK))
        transpose_scale<<<dim3(128, 128, BATCH), dim3(32, 8)>>>(p_p, p_inv, wout);

    // 6. hv = (v . E^T) * inv    (tf32 tensor cores)
    mm_av_tf32<<<dim3(32, 4, BATCH), 256>>>(p_v, p_p, p_inv, p_hv);

    // 7. out = x + (wp . hv + bp)  (3xTF32 split)
    mm_wh_tf32<<<dim3(32, 2, BATCH), 256>>>(wp, bp, p_hv, out, 1, x);
}

// round 8
// speedup vs baseline: 2.7567x; 1.0224x over previous
#include <cuda_runtime.h>
#include <cstdint>

#define NTOK 4096            // d*h*w = 16^3
#define CCH  256             // channels
#define BATCH 2
#define GRP  32
#define CPG  (CCH/GRP)       // 8
#define EPSV 1e-6f
#define SCALE 0.0625f        // 256^-0.5

// ---------------- scratch (device globals; no allocation allowed) ----------
__device__ unsigned g_hnh[BATCH*CCH*NTOK];        // tf32 split of groupnorm out
__device__ unsigned g_hnl[BATCH*CCH*NTOK];
__device__ float    g_q [BATCH*CCH*NTOK];         // tf32-rounded, pre-scaled
__device__ float    g_k [BATCH*CCH*NTOK];         // tf32-rounded
__device__ float    g_v [BATCH*CCH*NTOK];         // tf32-rounded
__device__ unsigned g_hvh[BATCH*CCH*NTOK];        // tf32 split of v.attn^T
__device__ unsigned g_hvl[BATCH*CCH*NTOK];
__device__ unsigned g_wth[4*CCH*CCH];             // W transposed [k][o], tf32 hi
__device__ unsigned g_wtl[4*CCH*CCH];             //                      tf32 lo
__device__ float    g_p [(size_t)BATCH*NTOK*NTOK]; // exp(S), tf32-rounded
__device__ float    g_sum[BATCH*NTOK];
__device__ float    g_inv[BATCH*NTOK];
__device__ float    g_stats[BATCH*GRP*2];

// ---------------- helpers --------------------------------------------------
__device__ __forceinline__ unsigned f2tf(float f) {
    unsigned u;
    asm("cvt.rna.tf32.f32 %0, %1;" : "=r"(u) : "f"(f));
    return u;
}

__device__ __forceinline__ void mma8(float* c, const unsigned* a, const unsigned* b) {
    asm volatile(
        "mma.sync.aligned.m16n8k8.row.col.f32.tf32.tf32.f32 "
        "{%0,%1,%2,%3}, {%4,%5,%6,%7}, {%8,%9}, {%0,%1,%2,%3};\n"
        : "+f"(c[0]), "+f"(c[1]), "+f"(c[2]), "+f"(c[3])
        : "r"(a[0]), "r"(a[1]), "r"(a[2]), "r"(a[3]),
          "r"(b[0]), "r"(b[1]));
}

// ---------------- zero accumulators ---------------------------------------
__global__ void zero_kernel()
{
    const int i = blockIdx.x * 256 + threadIdx.x;
    if (i < BATCH*NTOK) g_sum[i] = 0.f;
    if (i < BATCH*GRP*2) g_stats[i] = 0.f;
}

// ---------------- W prep: transpose to [k][o] and tf32-split ---------------
__global__ void prep_w(const float* __restrict__ w0, const float* __restrict__ w1,
                       const float* __restrict__ w2, const float* __restrict__ w3)
{
    const int m = blockIdx.y;
    const float* W = (m == 0) ? w0 : (m == 1) ? w1 : (m == 2) ? w2 : w3;
    const int o = blockIdx.x;
    const int k = threadIdx.x;
    const float f = W[o*CCH + k];               // coalesced read along k
    const unsigned h = f2tf(f);
    g_wth[m*CCH*CCH + k*CCH + o] = h;
    g_wtl[m*CCH*CCH + k*CCH + o] = f2tf(f - __uint_as_float(h));
}

// ---------------- GroupNorm pass 1: partial stats --------------------------
__global__ void gn_stats(const float* __restrict__ x)
{
    const int gidx  = blockIdx.x >> 3;
    const int chunk = blockIdx.x & 7;
    const float* xp = x + (size_t)gidx*CPG*NTOK + chunk*NTOK;
    const int tid = threadIdx.x;

    float s = 0.f, ss = 0.f;
    #pragma unroll
    for (int i = tid*4; i < NTOK; i += 1024) {
        float4 t = *(const float4*)(xp + i);
        s  += t.x + t.y + t.z + t.w;
        ss += t.x*t.x + t.y*t.y + t.z*t.z + t.w*t.w;
    }
    __shared__ float rs[256], rq[256];
    rs[tid] = s; rq[tid] = ss;
    __syncthreads();
    for (int off = 128; off; off >>= 1) {
        if (tid < off) { rs[tid] += rs[tid+off]; rq[tid] += rq[tid+off]; }
        __syncthreads();
    }
    if (tid == 0) {
        atomicAdd(&g_stats[2*gidx],   rs[0]);
        atomicAdd(&g_stats[2*gidx+1], rq[0]);
    }
}

// ---------------- GroupNorm pass 2: normalize + tf32-split write -----------
__global__ void gn_apply(const float* __restrict__ x,
                         const float* __restrict__ gamma,
                         const float* __restrict__ beta)
{
    const int c    = blockIdx.x & 255;
    const int gidx = (blockIdx.x >> 8) * GRP + (c >> 3);
    const float mu   = g_stats[2*gidx]   * (1.f/32768.f);
    const float var  = g_stats[2*gidx+1] * (1.f/32768.f) - mu*mu;
    const float rstd = rsqrtf(var + EPSV);
    const float ga = gamma[c]*rstd, be = beta[c];

    const size_t base = (size_t)blockIdx.x * NTOK;
    const int i = threadIdx.x * 4;
    #pragma unroll
    for (int s = 0; s < 4; s++) {
        float4 t = *(const float4*)(x + base + i + s*1024);
        float f[4];
        f[0] = (t.x - mu)*ga + be;
        f[1] = (t.y - mu)*ga + be;
        f[2] = (t.z - mu)*ga + be;
        f[3] = (t.w - mu)*ga + be;
        uint4 uh, ul;
        uh.x = f2tf(f[0]); ul.x = f2tf(f[0] - __uint_as_float(uh.x));
        uh.y = f2tf(f[1]); ul.y = f2tf(f[1] - __uint_as_float(uh.y));
        uh.z = f2tf(f[2]); ul.z = f2tf(f[2] - __uint_as_float(uh.z));
        uh.w = f2tf(f[3]); ul.w = f2tf(f[3] - __uint_as_float(uh.w));
        *(uint4*)(g_hnh + base + i + s*1024) = uh;
        *(uint4*)(g_hnl + base + i + s*1024) = ul;
    }
}

// ---------------- fused q/k/v projection, cvt-free 3xTF32 split ------------
// grid (32, 6, BATCH): blockIdx.y: 0,1->q  2,3->k  4,5->v
__global__ void __launch_bounds__(256)
mm_qkv(const float* __restrict__ bq,
       const float* __restrict__ bk,
       const float* __restrict__ bv)
{
    const int b   = blockIdx.z;
    const int sel = blockIdx.y >> 1;
    const int o0  = (blockIdx.y & 1) * 128;
    const int n0  = blockIdx.x * 128;

    const unsigned* Wh  = g_wth + sel*CCH*CCH;
    const unsigned* Wl  = g_wtl + sel*CCH*CCH;
    const unsigned* Bhg = g_hnh + (size_t)b*CCH*NTOK;
    const unsigned* Blg = g_hnl + (size_t)b*CCH*NTOK;
    float* O = ((sel == 0) ? g_q : (sel == 1) ? g_k : g_v) + (size_t)b*CCH*NTOK;
    const float* bias = (sel == 0) ? bq : (sel == 1) ? bk : bv;
    const float outScale = (sel == 0) ? SCALE : 1.f;

    __shared__ unsigned Ah[16][136], Al[16][136];   // [k][o]
    __shared__ unsigned Bh[16][136], Bl[16][136];   // [k][n]

    const int tid  = threadIdx.x;
    const int lane = tid & 31;
    const int wid  = tid >> 5;
    const int wr   = (wid & 1) * 64;
    const int wc   = (wid >> 1) * 32;
    const int lq   = lane >> 2;
    const int lr   = lane & 3;

    float acc[4][4][4] = {};

    for (int k0 = 0; k0 < CCH; k0 += 16) {
        #pragma unroll
        for (int s = 0; s < 2; s++) {
            int idx = tid + s*256;
            int kc = idx >> 5, c4 = (idx & 31) * 4;
            *(uint4*)&Ah[kc][c4] = *(const uint4*)(Wh  + (k0+kc)*CCH  + o0 + c4);
            *(uint4*)&Al[kc][c4] = *(const uint4*)(Wl  + (k0+kc)*CCH  + o0 + c4);
            *(uint4*)&Bh[kc][c4] = *(const uint4*)(Bhg + (size_t)(k0+kc)*NTOK + n0 + c4);
            *(uint4*)&Bl[kc][c4] = *(const uint4*)(Blg + (size_t)(k0+kc)*NTOK + n0 + c4);
        }
        __syncthreads();
        #pragma unroll
        for (int kk = 0; kk < 16; kk += 8) {
            unsigned bh[4][2], bl[4][2];
            #pragma unroll
            for (int nt = 0; nt < 4; nt++) {
                int col = wc + nt*8 + lq;
                bh[nt][0] = Bh[kk + lr    ][col];
                bh[nt][1] = Bh[kk + 4 + lr][col];
                bl[nt][0] = Bl[kk + lr    ][col];
                bl[nt][1] = Bl[kk + 4 + lr][col];
            }
            #pragma unroll
            for (int mt = 0; mt < 4; mt++) {
                unsigned ah[4], al[4];
                int rb = wr + mt*16 + lq;
                ah[0] = Ah[kk + lr    ][rb];   ah[1] = Ah[kk + lr    ][rb + 8];
                ah[2] = Ah[kk + 4 + lr][rb];   ah[3] = Ah[kk + 4 + lr][rb + 8];
                al[0] = Al[kk + lr    ][rb];   al[1] = Al[kk + lr    ][rb + 8];
                al[2] = Al[kk + 4 + lr][rb];   al[3] = Al[kk + 4 + lr][rb + 8];
                #pragma unroll
                for (int nt = 0; nt < 4; nt++) {
                    mma8(acc[mt][nt], ah, bh[nt]);
                    mma8(acc[mt][nt], ah, bl[nt]);
                    mma8(acc[mt][nt], al, bh[nt]);
                }
            }
        }
        __syncthreads();
    }

    // epilogue: (acc + bias) * outScale, tf32-rounded (consumers are tf32)
    #pragma unroll
    for (int mt = 0; mt < 4; mt++) {
        const int o = o0 + wr + mt*16 + lq;
        const float bi0 = bias[o], bi1 = bias[o+8];
        #pragma unroll
        for (int nt = 0; nt < 4; nt++) {
            const int n = n0 + wc + nt*8 + 2*lr;
            float2 v0, v1;
            v0.x = __uint_as_float(f2tf((acc[mt][nt][0] + bi0) * outScale));
            v0.y = __uint_as_float(f2tf((acc[mt][nt][1] + bi0) * outScale));
            v1.x = __uint_as_float(f2tf((acc[mt][nt][2] + bi1) * outScale));
            v1.y = __uint_as_float(f2tf((acc[mt][nt][3] + bi1) * outScale));
            *(float2*)(O + (size_t)o*NTOK + n)     = v0;
            *(float2*)(O + (size_t)(o+8)*NTOK + n) = v1;
        }
    }
}

// ---------------- output projection + residual, cvt-free 3xTF32 split ------
__global__ void __launch_bounds__(256)
mm_proj(const float* __restrict__ bias,
        const float* __restrict__ Xbase,
        float* __restrict__ Obase)
{
    const int b  = blockIdx.z;
    const unsigned* Wh  = g_wth + 3*CCH*CCH;
    const unsigned* Wl  = g_wtl + 3*CCH*CCH;
    const unsigned* Bhg = g_hvh + (size_t)b*CCH*NTOK;
    const unsigned* Blg = g_hvl + (size_t)b*CCH*NTOK;
    const float* X = Xbase + (size_t)b*CCH*NTOK;
    float*       O = Obase + (size_t)b*CCH*NTOK;
    const int o0 = blockIdx.y * 128;
    const int n0 = blockIdx.x * 128;

    __shared__ unsigned Ah[16][136], Al[16][136];
    __shared__ unsigned Bh[16][136], Bl[16][136];

    const int tid  = threadIdx.x;
    const int lane = tid & 31;
    const int wid  = tid >> 5;
    const int wr   = (wid & 1) * 64;
    const int wc   = (wid >> 1) * 32;
    const int lq   = lane >> 2;
    const int lr   = lane & 3;

    float acc[4][4][4] = {};

    for (int k0 = 0; k0 < CCH; k0 += 16) {
        #pragma unroll
        for (int s = 0; s < 2; s++) {
            int idx = tid + s*256;
            int kc = idx >> 5, c4 = (idx & 31) * 4;
            *(uint4*)&Ah[kc][c4] = *(const uint4*)(Wh  + (k0+kc)*CCH  + o0 + c4);
            *(uint4*)&Al[kc][c4] = *(const uint4*)(Wl  + (k0+kc)*CCH  + o0 + c4);
            *(uint4*)&Bh[kc][c4] = *(const uint4*)(Bhg + (size_t)(k0+kc)*NTOK + n0 + c4);
            *(uint4*)&Bl[kc][c4] = *(const uint4*)(Blg + (size_t)(k0+kc)*NTOK + n0 + c4);
        }
        __syncthreads();
        #pragma unroll
        for (int kk = 0; kk < 16; kk += 8) {
            unsigned bh[4][2], bl[4][2];
            #pragma unroll
            for (int nt = 0; nt < 4; nt++) {
                int col = wc + nt*8 + lq;
                bh[nt][0] = Bh[kk + lr    ][col];
                bh[nt][1] = Bh[kk + 4 + lr][col];
                bl[nt][0] = Bl[kk + lr    ][col];
                bl[nt][1] = Bl[kk + 4 + lr][col];
            }
            #pragma unroll
            for (int mt = 0; mt < 4; mt++) {
                unsigned ah[4], al[4];
                int rb = wr + mt*16 + lq;
                ah[0] = Ah[kk + lr    ][rb];   ah[1] = Ah[kk + lr    ][rb + 8];
                ah[2] = Ah[kk + 4 + lr][rb];   ah[3] = Ah[kk + 4 + lr][rb + 8];
                al[0] = Al[kk + lr    ][rb];   al[1] = Al[kk + lr    ][rb + 8];
                al[2] = Al[kk + 4 + lr][rb];   al[3] = Al[kk + 4 + lr][rb + 8];
                #pragma unroll
                for (int nt = 0; nt < 4; nt++) {
                    mma8(acc[mt][nt], ah, bh[nt]);
                    mma8(acc[mt][nt], ah, bl[nt]);
                    mma8(acc[mt][nt], al, bh[nt]);
                }
            }
        }
        __syncthreads();
    }

    #pragma unroll
    for (int mt = 0; mt < 4; mt++) {
        const int o = o0 + wr + mt*16 + lq;
        const float bi0 = bias[o], bi1 = bias[o+8];
        #pragma unroll
        for (int nt = 0; nt < 4; nt++) {
            const int n = n0 + wc + nt*8 + 2*lr;
            float2 x0 = *(const float2*)(X + (size_t)o*NTOK + n);
            float2 x1 = *(const float2*)(X + (size_t)(o+8)*NTOK + n);
            float2 v0, v1;
            v0.x = acc[mt][nt][0] + bi0 + x0.x;  v0.y = acc[mt][nt][1] + bi0 + x0.y;
            v1.x = acc[mt][nt][2] + bi1 + x1.x;  v1.y = acc[mt][nt][3] + bi1 + x1.y;
            *(float2*)(O + (size_t)o*NTOK + n)     = v0;
            *(float2*)(O + (size_t)(o+8)*NTOK + n) = v1;
        }
    }
}

// ---------------- E[n][m] = exp(q^T k); cvt-free, k-chunk 32 ---------------
// q pre-scaled by SCALE and tf32-rounded; k tf32-rounded
__global__ void __launch_bounds__(256, 2)
mm_s_tf32(float* __restrict__ E)
{
    const int b = blockIdx.z;
    const unsigned* Q  = (const unsigned*)g_q + (size_t)b*CCH*NTOK;
    const unsigned* Kp = (const unsigned*)g_k + (size_t)b*CCH*NTOK;
    float*          Eb = E + (size_t)b*NTOK*NTOK;
    const int n0 = blockIdx.y * 128;
    const int m0 = blockIdx.x * 128;

    __shared__ unsigned As[32][136];   // [k][n]
    __shared__ unsigned Bs[32][136];   // [k][m]

    const int tid  = threadIdx.x;
    const int lane = tid & 31;
    const int wid  = tid >> 5;
    const int wr   = (wid & 1) * 64;
    const int wc   = (wid >> 1) * 32;
    const int lq   = lane >> 2;
    const int lr   = lane & 3;

    float acc[4][4][4] = {};

    for (int k0 = 0; k0 < CCH; k0 += 32) {
        #pragma unroll
        for (int s = 0; s < 4; s++) {
            int idx = tid + s*256;
            int kc = idx >> 5, c4 = (idx & 31) * 4;
            *(uint4*)&As[kc][c4] = *(const uint4*)(Q  + (size_t)(k0+kc)*NTOK + n0 + c4);
            *(uint4*)&Bs[kc][c4] = *(const uint4*)(Kp + (size_t)(k0+kc)*NTOK + m0 + c4);
        }
        __syncthreads();
        #pragma unroll
        for (int kk = 0; kk < 32; kk += 8) {
            unsigned bfr[4][2];
            #pragma unroll
            for (int nt = 0; nt < 4; nt++) {
                int col = wc + nt*8 + lq;
                bfr[nt][0] = Bs[kk + lr    ][col];
                bfr[nt][1] = Bs[kk + 4 + lr][col];
            }
            #pragma unroll
            for (int mt = 0; mt < 4; mt++) {
                unsigned afr[4];
                int rb = wr + mt*16 + lq;
                afr[0] = As[kk + lr    ][rb];
                afr[1] = As[kk + lr    ][rb + 8];
                afr[2] = As[kk + 4 + lr][rb];
                afr[3] = As[kk + 4 + lr][rb + 8];
                #pragma unroll
                for (int nt = 0; nt < 4; nt++)
                    mma8(acc[mt][nt], afr, bfr[nt]);
            }
        }
        __syncthreads();
    }

    // epilogue: E = tf32round(exp(acc)); fused row-sum atomics
    #pragma unroll
    for (int mt = 0; mt < 4; mt++) {
        const size_t n = n0 + wr + mt*16 + lq;
        float rs0 = 0.f, rs1 = 0.f;
        #pragma unroll
        for (int nt = 0; nt < 4; nt++) {
            const int m = m0 + wc + nt*8 + 2*lr;
            float2 v0, v1;
            v0.x = __uint_as_float(f2tf(__expf(acc[mt][nt][0])));
            v0.y = __uint_as_float(f2tf(__expf(acc[mt][nt][1])));
            v1.x = __uint_as_float(f2tf(__expf(acc[mt][nt][2])));
            v1.y = __uint_as_float(f2tf(__expf(acc[mt][nt][3])));
            rs0 += v0.x + v0.y;
            rs1 += v1.x + v1.y;
            *(float2*)(Eb + n*NTOK + m)     = v0;
            *(float2*)(Eb + (n+8)*NTOK + m) = v1;
        }
        rs0 += __shfl_xor_sync(0xffffffffu, rs0, 1);
        rs0 += __shfl_xor_sync(0xffffffffu, rs0, 2);
        rs1 += __shfl_xor_sync(0xffffffffu, rs1, 1);
        rs1 += __shfl_xor_sync(0xffffffffu, rs1, 2);
        if (lr == 0) {
            atomicAdd(&g_sum[b*NTOK + n],     rs0);
            atomicAdd(&g_sum[b*NTOK + n + 8], rs1);
        }
    }
}

// ---------------- inv[i] = 1/sum[i] ----------------------------------------
__global__ void inv_kernel()
{
    const int i = blockIdx.x * 256 + threadIdx.x;
    if (i < BATCH*NTOK) g_inv[i] = 1.f / g_sum[i];
}

// ---------------- wout[b][m][n] = E[b][n][m] * inv[b][n] -------------------
__global__ void transpose_scale(const float* __restrict__ E,
                                const float* __restrict__ inv,
                                float* __restrict__ Wout)
{
    __shared__ float t[32][33];
    __shared__ float is[32];
    const int b = blockIdx.z;
    const float* Eb = E    + (size_t)b*NTOK*NTOK;
    float*       Wb = Wout + (size_t)b*NTOK*NTOK;
    const int m0 = blockIdx.x * 32;
    const int n0 = blockIdx.y * 32;
    const int x = threadIdx.x, y = threadIdx.y;   // 32 x 8
    if (y == 0) is[x] = inv[b*NTOK + n0 + x];
    #pragma unroll
    for (int i = 0; i < 32; i += 8)
        t[y+i][x] = Eb[(size_t)(n0+y+i)*NTOK + m0 + x];
    __syncthreads();
    #pragma unroll
    for (int i = 0; i < 32; i += 8)
        Wb[(size_t)(m0+y+i)*NTOK + n0 + x] = t[x][y+i] * is[x];
}

// ---------------- hv[c][n] = inv[n] * sum_m V[c][m] * E[n][m], cvt-free ----
// outputs tf32 hi/lo split for the projection GEMM
__global__ void __launch_bounds__(256)
mm_av_tf32(const float* __restrict__ E)
{
    const int b = blockIdx.z;
    const unsigned* V  = (const unsigned*)g_v + (size_t)b*CCH*NTOK;
    const unsigned* Eb = (const unsigned*)E   + (size_t)b*NTOK*NTOK;
    unsigned* Oh = g_hvh + (size_t)b*CCH*NTOK;
    unsigned* Ol = g_hvl + (size_t)b*CCH*NTOK;
    const int c0 = blockIdx.y * 64;
    const int n0 = blockIdx.x * 128;

    __shared__ unsigned As[64][20];    // [c][k]  (V)
    __shared__ unsigned Bs[128][20];   // [n][k]  (E)
    __shared__ float    invs[128];

    const int tid  = threadIdx.x;
    const int lane = tid & 31;
    const int wid  = tid >> 5;
    const int wr   = (wid & 1) * 32;
    const int wc   = (wid >> 1) * 32;
    const int lq   = lane >> 2;
    const int lr   = lane & 3;

    if (tid < 128) invs[tid] = g_inv[b*NTOK + n0 + tid];

    float acc[2][4][4] = {};

    for (int m0i = 0; m0i < NTOK; m0i += 16) {
        {
            int c = tid >> 2, k4 = (tid & 3) * 4;
            *(uint4*)&As[c][k4] = *(const uint4*)(V + (size_t)(c0+c)*NTOK + m0i + k4);
        }
        #pragma unroll
        for (int s = 0; s < 2; s++) {
            int idx = tid + s*256;
            int n = idx >> 2, k4 = (idx & 3) * 4;
            *(uint4*)&Bs[n][k4] = *(const uint4*)(Eb + (size_t)(n0+n)*NTOK + m0i + k4);
        }
        __syncthreads();
        #pragma unroll
        for (int kk = 0; kk < 16; kk += 8) {
            unsigned bfr[4][2];
            #pragma unroll
            for (int nt = 0; nt < 4; nt++) {
                int col = wc + nt*8 + lq;
                bfr[nt][0] = Bs[col][kk + lr];
                bfr[nt][1] = Bs[col][kk + 4 + lr];
            }
            #pragma unroll
            for (int mt = 0; mt < 2; mt++) {
                unsigned afr[4];
                int rb = wr + mt*16 + lq;
                afr[0] = As[rb    ][kk + lr];
                afr[1] = As[rb + 8][kk + lr];
                afr[2] = As[rb    ][kk + 4 + lr];
                afr[3] = As[rb + 8][kk + 4 + lr];
                #pragma unroll
                for (int nt = 0; nt < 4; nt++)
                    mma8(acc[mt][nt], afr, bfr[nt]);
            }
        }
        __syncthreads();
    }

    #pragma unroll
    for (int mt = 0; mt < 2; mt++) {
        const int row = wr + mt*16 + lq;
        #pragma unroll
        for (int nt = 0; nt < 4; nt++) {
            const int nl = wc + nt*8 + 2*lr;
            const float i0 = invs[nl], i1 = invs[nl+1];
            float vv[4];
            vv[0] = acc[mt][nt][0] * i0;  vv[1] = acc[mt][nt][1] * i1;
            vv[2] = acc[mt][nt][2] * i0;  vv[3] = acc[mt][nt][3] * i1;
            unsigned h0 = f2tf(vv[0]), h1 = f2tf(vv[1]);
            unsigned h2 = f2tf(vv[2]), h3 = f2tf(vv[3]);
            uint2 uh0 = {h0, h1}, uh1 = {h2, h3};
            uint2 ul0 = {f2tf(vv[0]-__uint_as_float(h0)), f2tf(vv[1]-__uint_as_float(h1))};
            uint2 ul1 = {f2tf(vv[2]-__uint_as_float(h2)), f2tf(vv[3]-__uint_as_float(h3))};
            *(uint2*)(Oh + (size_t)(c0+row  )*NTOK + n0 + nl) = uh0;
            *(uint2*)(Oh + (size_t)(c0+row+8)*NTOK + n0 + nl) = uh1;
            *(uint2*)(Ol + (size_t)(c0+row  )*NTOK + n0 + nl) = ul0;
            *(uint2*)(Ol + (size_t)(c0+row+8)*NTOK + n0 + nl) = ul1;
        }
    }
}

// ---------------------------------------------------------------------------
extern "C" void kernel_launch(void* const* d_in, const int* in_sizes, int n_in,
                              void* d_out, int out_size)
{
    const float* x     = (const float*)d_in[0];
    const float* gamma = (const float*)d_in[1];
    const float* beta  = (const float*)d_in[2];
    const float* wq = (const float*)d_in[3];  const float* bq = (const float*)d_in[4];
    const float* wk = (const float*)d_in[5];  const float* bk = (const float*)d_in[6];
    const float* wv = (const float*)d_in[7];  const float* bv = (const float*)d_in[8];
    const float* wp = (const float*)d_in[9];  const float* bp = (const float*)d_in[10];

    float* out  = (float*)d_out;                              // (2,256,4096)
    float* wout = out + (size_t)BATCH*CCH*NTOK;               // (2,4096,4096)

    float *p_p, *p_inv;
    cudaGetSymbolAddress((void**)&p_p,   g_p);
    cudaGetSymbolAddress((void**)&p_inv, g_inv);

    // 0. zero accumulators; transpose+split weights (tiny)
    zero_kernel<<<33, 256>>>();
    prep_w<<<dim3(CCH, 4), CCH>>>(wq, wk, wv, wp);

    // 1. GroupNorm (two-pass; pass 2 writes tf32 hi/lo directly)
    gn_stats<<<BATCH*GRP*8, 256>>>(x);
    gn_apply<<<BATCH*CCH, 256>>>(x, gamma, beta);

    // 2. fused q/k/v projections (cvt-free 3xTF32 split; q pre-scaled)
    mm_qkv<<<dim3(32, 6, BATCH), 256>>>(bq, bk, bv);

    // 3. E = exp(q^T k) with fused row sums (cvt-free)
    mm_s_tf32<<<dim3(32, 32, BATCH), 256>>>(p_p);

    // 4. reciprocal of row sums
    inv_kernel<<<32, 256>>>();

    // 5. returned attention = normalize + transpose
    if (out_size >= (int)((size_t)BATCH*CCH*NTOK + (size_t)BATCH*NTOK*NTOK))
        transpose_scale<<<dim3(128, 128, BATCH), dim3(32, 8)>>>(p_p, p_inv, wout);

    // 6. hv = (v . E^T) * inv, writes tf32 hi/lo split (cvt-free)
    mm_av_tf32<<<dim3(32, 4, BATCH), 256>>>(p_p);

    // 7. out = x + (wp . hv + bp)  (cvt-free 3xTF32 split)
    mm_proj<<<dim3(32, 2, BATCH), 256>>>(bp, x, out);
}

// round 12
// speedup vs baseline: 3.1791x; 1.1532x over previous
#include <cuda_runtime.h>
#include <cstdint>

#define NTOK 4096            // d*h*w = 16^3
#define CCH  256             // channels
#define BATCH 2
#define GRP  32
#define CPG  (CCH/GRP)       // 8
#define EPSV 1e-6f
#define SCALE 0.0625f        // 256^-0.5

// ---------------- scratch (device globals; no allocation allowed) ----------
__device__ unsigned g_hnh[BATCH*CCH*NTOK];        // tf32 split of groupnorm out
__device__ unsigned g_hnl[BATCH*CCH*NTOK];
__device__ float    g_q [BATCH*CCH*NTOK];         // tf32-rounded, pre-scaled
__device__ float    g_k [BATCH*CCH*NTOK];         // tf32-rounded
__device__ float    g_v [BATCH*CCH*NTOK];         // tf32-rounded
__device__ unsigned g_hvh[BATCH*CCH*NTOK];        // tf32 split of v.attn^T
__device__ unsigned g_hvl[BATCH*CCH*NTOK];
__device__ unsigned g_wth[4*CCH*CCH];             // W transposed [k][o], tf32 hi
__device__ unsigned g_wtl[4*CCH*CCH];             //                      tf32 lo
__device__ float    g_p [(size_t)BATCH*NTOK*NTOK]; // exp(S), tf32-rounded
__device__ float    g_sum[BATCH*NTOK];
__device__ float    g_inv[BATCH*NTOK];
__device__ float    g_stats[BATCH*GRP*2];

// ---------------- helpers --------------------------------------------------
__device__ __forceinline__ unsigned f2tf(float f) {
    unsigned u;
    asm("cvt.rna.tf32.f32 %0, %1;" : "=r"(u) : "f"(f));
    return u;
}

__device__ __forceinline__ void mma8(float* c, const unsigned* a, const unsigned* b) {
    asm volatile(
        "mma.sync.aligned.m16n8k8.row.col.f32.tf32.tf32.f32 "
        "{%0,%1,%2,%3}, {%4,%5,%6,%7}, {%8,%9}, {%0,%1,%2,%3};\n"
        : "+f"(c[0]), "+f"(c[1]), "+f"(c[2]), "+f"(c[3])
        : "r"(a[0]), "r"(a[1]), "r"(a[2]), "r"(a[3]),
          "r"(b[0]), "r"(b[1]));
}

__device__ __forceinline__ void cpa16(void* smem, const void* gmem) {
    unsigned saddr = (unsigned)__cvta_generic_to_shared(smem);
    asm volatile("cp.async.cg.shared.global [%0], [%1], 16;\n" :: "r"(saddr), "l"(gmem));
}
#define CPA_COMMIT asm volatile("cp.async.commit_group;\n" ::: "memory")
#define CPA_WAIT1  asm volatile("cp.async.wait_group 1;\n" ::: "memory")
#define CPA_WAIT0  asm volatile("cp.async.wait_group 0;\n" ::: "memory")

// ---------------- zero accumulators ---------------------------------------
__global__ void zero_kernel()
{
    const int i = blockIdx.x * 256 + threadIdx.x;
    if (i < BATCH*NTOK) g_sum[i] = 0.f;
    if (i < BATCH*GRP*2) g_stats[i] = 0.f;
}

// ---------------- W prep: transpose to [k][o] and tf32-split ---------------
__global__ void prep_w(const float* __restrict__ w0, const float* __restrict__ w1,
                       const float* __restrict__ w2, const float* __restrict__ w3)
{
    const int m = blockIdx.y;
    const float* W = (m == 0) ? w0 : (m == 1) ? w1 : (m == 2) ? w2 : w3;
    const int o = blockIdx.x;
    const int k = threadIdx.x;
    const float f = W[o*CCH + k];
    const unsigned h = f2tf(f);
    g_wth[m*CCH*CCH + k*CCH + o] = h;
    g_wtl[m*CCH*CCH + k*CCH + o] = f2tf(f - __uint_as_float(h));
}

// ---------------- GroupNorm pass 1: partial stats --------------------------
__global__ void gn_stats(const float* __restrict__ x)
{
    const int gidx  = blockIdx.x >> 3;
    const int chunk = blockIdx.x & 7;
    const float* xp = x + (size_t)gidx*CPG*NTOK + chunk*NTOK;
    const int tid = threadIdx.x;

    float s = 0.f, ss = 0.f;
    #pragma unroll
    for (int i = tid*4; i < NTOK; i += 1024) {
        float4 t = *(const float4*)(xp + i);
        s  += t.x + t.y + t.z + t.w;
        ss += t.x*t.x + t.y*t.y + t.z*t.z + t.w*t.w;
    }
    __shared__ float rs[256], rq[256];
    rs[tid] = s; rq[tid] = ss;
    __syncthreads();
    for (int off = 128; off; off >>= 1) {
        if (tid < off) { rs[tid] += rs[tid+off]; rq[tid] += rq[tid+off]; }
        __syncthreads();
    }
    if (tid == 0) {
        atomicAdd(&g_stats[2*gidx],   rs[0]);
        atomicAdd(&g_stats[2*gidx+1], rq[0]);
    }
}

// ---------------- GroupNorm pass 2: normalize + tf32-split write -----------
__global__ void gn_apply(const float* __restrict__ x,
                         const float* __restrict__ gamma,
                         const float* __restrict__ beta)
{
    const int c    = blockIdx.x & 255;
    const int gidx = (blockIdx.x >> 8) * GRP + (c >> 3);
    const float mu   = g_stats[2*gidx]   * (1.f/32768.f);
    const float var  = g_stats[2*gidx+1] * (1.f/32768.f) - mu*mu;
    const float rstd = rsqrtf(var + EPSV);
    const float ga = gamma[c]*rstd, be = beta[c];

    const size_t base = (size_t)blockIdx.x * NTOK;
    const int i = threadIdx.x * 4;
    #pragma unroll
    for (int s = 0; s < 4; s++) {
        float4 t = *(const float4*)(x + base + i + s*1024);
        float f[4];
        f[0] = (t.x - mu)*ga + be;
        f[1] = (t.y - mu)*ga + be;
        f[2] = (t.z - mu)*ga + be;
        f[3] = (t.w - mu)*ga + be;
        uint4 uh, ul;
        uh.x = f2tf(f[0]); ul.x = f2tf(f[0] - __uint_as_float(uh.x));
        uh.y = f2tf(f[1]); ul.y = f2tf(f[1] - __uint_as_float(uh.y));
        uh.z = f2tf(f[2]); ul.z = f2tf(f[2] - __uint_as_float(uh.z));
        uh.w = f2tf(f[3]); ul.w = f2tf(f[3] - __uint_as_float(uh.w));
        *(uint4*)(g_hnh + base + i + s*1024) = uh;
        *(uint4*)(g_hnl + base + i + s*1024) = ul;
    }
}

// ---------------- fused q/k/v projection, cvt-free 3xTF32 split ------------
__global__ void __launch_bounds__(256)
mm_qkv(const float* __restrict__ bq,
       const float* __restrict__ bk,
       const float* __restrict__ bv)
{
    const int b   = blockIdx.z;
    const int sel = blockIdx.y >> 1;
    const int o0  = (blockIdx.y & 1) * 128;
    const int n0  = blockIdx.x * 128;

    const unsigned* Wh  = g_wth + sel*CCH*CCH;
    const unsigned* Wl  = g_wtl + sel*CCH*CCH;
    const unsigned* Bhg = g_hnh + (size_t)b*CCH*NTOK;
    const unsigned* Blg = g_hnl + (size_t)b*CCH*NTOK;
    float* O = ((sel == 0) ? g_q : (sel == 1) ? g_k : g_v) + (size_t)b*CCH*NTOK;
    const float* bias = (sel == 0) ? bq : (sel == 1) ? bk : bv;
    const float outScale = (sel == 0) ? SCALE : 1.f;

    __shared__ unsigned Ah[16][136], Al[16][136];
    __shared__ unsigned Bh[16][136], Bl[16][136];

    const int tid  = threadIdx.x;
    const int lane = tid & 31;
    const int wid  = tid >> 5;
    const int wr   = (wid & 1) * 64;
    const int wc   = (wid >> 1) * 32;
    const int lq   = lane >> 2;
    const int lr   = lane & 3;

    float acc[4][4][4] = {};

    for (int k0 = 0; k0 < CCH; k0 += 16) {
        #pragma unroll
        for (int s = 0; s < 2; s++) {
            int idx = tid + s*256;
            int kc = idx >> 5, c4 = (idx & 31) * 4;
            *(uint4*)&Ah[kc][c4] = *(const uint4*)(Wh  + (k0+kc)*CCH  + o0 + c4);
            *(uint4*)&Al[kc][c4] = *(const uint4*)(Wl  + (k0+kc)*CCH  + o0 + c4);
            *(uint4*)&Bh[kc][c4] = *(const uint4*)(Bhg + (size_t)(k0+kc)*NTOK + n0 + c4);
            *(uint4*)&Bl[kc][c4] = *(const uint4*)(Blg + (size_t)(k0+kc)*NTOK + n0 + c4);
        }
        __syncthreads();
        #pragma unroll
        for (int kk = 0; kk < 16; kk += 8) {
            unsigned bh[4][2], bl[4][2];
            #pragma unroll
            for (int nt = 0; nt < 4; nt++) {
                int col = wc + nt*8 + lq;
                bh[nt][0] = Bh[kk + lr    ][col];
                bh[nt][1] = Bh[kk + 4 + lr][col];
                bl[nt][0] = Bl[kk + lr    ][col];
                bl[nt][1] = Bl[kk + 4 + lr][col];
            }
            #pragma unroll
            for (int mt = 0; mt < 4; mt++) {
                unsigned ah[4], al[4];
                int rb = wr + mt*16 + lq;
                ah[0] = Ah[kk + lr    ][rb];   ah[1] = Ah[kk + lr    ][rb + 8];
                ah[2] = Ah[kk + 4 + lr][rb];   ah[3] = Ah[kk + 4 + lr][rb + 8];
                al[0] = Al[kk + lr    ][rb];   al[1] = Al[kk + lr    ][rb + 8];
                al[2] = Al[kk + 4 + lr][rb];   al[3] = Al[kk + 4 + lr][rb + 8];
                #pragma unroll
                for (int nt = 0; nt < 4; nt++) {
                    mma8(acc[mt][nt], ah, bh[nt]);
                    mma8(acc[mt][nt], ah, bl[nt]);
                    mma8(acc[mt][nt], al, bh[nt]);
                }
            }
        }
        __syncthreads();
    }

    #pragma unroll
    for (int mt = 0; mt < 4; mt++) {
        const int o = o0 + wr + mt*16 + lq;
        const float bi0 = bias[o], bi1 = bias[o+8];
        #pragma unroll
        for (int nt = 0; nt < 4; nt++) {
            const int n = n0 + wc + nt*8 + 2*lr;
            float2 v0, v1;
            v0.x = __uint_as_float(f2tf((acc[mt][nt][0] + bi0) * outScale));
            v0.y = __uint_as_float(f2tf((acc[mt][nt][1] + bi0) * outScale));
            v1.x = __uint_as_float(f2tf((acc[mt][nt][2] + bi1) * outScale));
            v1.y = __uint_as_float(f2tf((acc[mt][nt][3] + bi1) * outScale));
            *(float2*)(O + (size_t)o*NTOK + n)     = v0;
            *(float2*)(O + (size_t)(o+8)*NTOK + n) = v1;
        }
    }
}

// ---------------- output projection + residual, cvt-free 3xTF32 split ------
__global__ void __launch_bounds__(256)
mm_proj(const float* __restrict__ bias,
        const float* __restrict__ Xbase,
        float* __restrict__ Obase)
{
    const int b  = blockIdx.z;
    const unsigned* Wh  = g_wth + 3*CCH*CCH;
    const unsigned* Wl  = g_wtl + 3*CCH*CCH;
    const unsigned* Bhg = g_hvh + (size_t)b*CCH*NTOK;
    const unsigned* Blg = g_hvl + (size_t)b*CCH*NTOK;
    const float* X = Xbase + (size_t)b*CCH*NTOK;
    float*       O = Obase + (size_t)b*CCH*NTOK;
    const int o0 = blockIdx.y * 128;
    const int n0 = blockIdx.x * 128;

    __shared__ unsigned Ah[16][136], Al[16][136];
    __shared__ unsigned Bh[16][136], Bl[16][136];

    const int tid  = threadIdx.x;
    const int lane = tid & 31;
    const int wid  = tid >> 5;
    const int wr   = (wid & 1) * 64;
    const int wc   = (wid >> 1) * 32;
    const int lq   = lane >> 2;
    const int lr   = lane & 3;

    float acc[4][4][4] = {};

    for (int k0 = 0; k0 < CCH; k0 += 16) {
        #pragma unroll
        for (int s = 0; s < 2; s++) {
            int idx = tid + s*256;
            int kc = idx >> 5, c4 = (idx & 31) * 4;
            *(uint4*)&Ah[kc][c4] = *(const uint4*)(Wh  + (k0+kc)*CCH  + o0 + c4);
            *(uint4*)&Al[kc][c4] = *(const uint4*)(Wl  + (k0+kc)*CCH  + o0 + c4);
            *(uint4*)&Bh[kc][c4] = *(const uint4*)(Bhg + (size_t)(k0+kc)*NTOK + n0 + c4);
            *(uint4*)&Bl[kc][c4] = *(const uint4*)(Blg + (size_t)(k0+kc)*NTOK + n0 + c4);
        }
        __syncthreads();
        #pragma unroll
        for (int kk = 0; kk < 16; kk += 8) {
            unsigned bh[4][2], bl[4][2];
            #pragma unroll
            for (int nt = 0; nt < 4; nt++) {
                int col = wc + nt*8 + lq;
                bh[nt][0] = Bh[kk + lr    ][col];
                bh[nt][1] = Bh[kk + 4 + lr][col];
                bl[nt][0] = Bl[kk + lr    ][col];
                bl[nt][1] = Bl[kk + 4 + lr][col];
            }
            #pragma unroll
            for (int mt = 0; mt < 4; mt++) {
                unsigned ah[4], al[4];
                int rb = wr + mt*16 + lq;
                ah[0] = Ah[kk + lr    ][rb];   ah[1] = Ah[kk + lr    ][rb + 8];
                ah[2] = Ah[kk + 4 + lr][rb];   ah[3] = Ah[kk + 4 + lr][rb + 8];
                al[0] = Al[kk + lr    ][rb];   al[1] = Al[kk + lr    ][rb + 8];
                al[2] = Al[kk + 4 + lr][rb];   al[3] = Al[kk + 4 + lr][rb + 8];
                #pragma unroll
                for (int nt = 0; nt < 4; nt++) {
                    mma8(acc[mt][nt], ah, bh[nt]);
                    mma8(acc[mt][nt], ah, bl[nt]);
                    mma8(acc[mt][nt], al, bh[nt]);
                }
            }
        }
        __syncthreads();
    }

    #pragma unroll
    for (int mt = 0; mt < 4; mt++) {
        const int o = o0 + wr + mt*16 + lq;
        const float bi0 = bias[o], bi1 = bias[o+8];
        #pragma unroll
        for (int nt = 0; nt < 4; nt++) {
            const int n = n0 + wc + nt*8 + 2*lr;
            float2 x0 = *(const float2*)(X + (size_t)o*NTOK + n);
            float2 x1 = *(const float2*)(X + (size_t)(o+8)*NTOK + n);
            float2 v0, v1;
            v0.x = acc[mt][nt][0] + bi0 + x0.x;  v0.y = acc[mt][nt][1] + bi0 + x0.y;
            v1.x = acc[mt][nt][2] + bi1 + x1.x;  v1.y = acc[mt][nt][3] + bi1 + x1.y;
            *(float2*)(O + (size_t)o*NTOK + n)     = v0;
            *(float2*)(O + (size_t)(o+8)*NTOK + n) = v1;
        }
    }
}

// ---------------- E[n][m] = exp(q^T k); cp.async double-buffered -----------
__global__ void __launch_bounds__(256, 2)
mm_s_tf32(float* __restrict__ E)
{
    const int b = blockIdx.z;
    const unsigned* Q  = (const unsigned*)g_q + (size_t)b*CCH*NTOK;
    const unsigned* Kp = (const unsigned*)g_k + (size_t)b*CCH*NTOK;
    float*          Eb = E + (size_t)b*NTOK*NTOK;
    const int n0 = blockIdx.y * 128;
    const int m0 = blockIdx.x * 128;

    __shared__ unsigned As[2][16][136];   // [buf][k][n]
    __shared__ unsigned Bs[2][16][136];   // [buf][k][m]

    const int tid  = threadIdx.x;
    const int lane = tid & 31;
    const int wid  = tid >> 5;
    const int wr   = (wid & 1) * 64;
    const int wc   = (wid >> 1) * 32;
    const int lq   = lane >> 2;
    const int lr   = lane & 3;

    const int lkc0 = tid >> 5,        lc4 = (tid & 31) * 4;   // s=0
    const int lkc1 = (tid + 256) >> 5;                        // s=1

    float acc[4][4][4] = {};

    // prologue: stage 0
    {
        cpa16(&As[0][lkc0][lc4], Q  + (size_t)lkc0*NTOK + n0 + lc4);
        cpa16(&Bs[0][lkc0][lc4], Kp + (size_t)lkc0*NTOK + m0 + lc4);
        cpa16(&As[0][lkc1][lc4], Q  + (size_t)lkc1*NTOK + n0 + lc4);
        cpa16(&Bs[0][lkc1][lc4], Kp + (size_t)lkc1*NTOK + m0 + lc4);
        CPA_COMMIT;
    }

    for (int it = 0; it < 16; it++) {
        const int buf = it & 1;
        if (it + 1 < 16) {
            const int k0 = (it + 1) * 16;
            cpa16(&As[buf^1][lkc0][lc4], Q  + (size_t)(k0+lkc0)*NTOK + n0 + lc4);
            cpa16(&Bs[buf^1][lkc0][lc4], Kp + (size_t)(k0+lkc0)*NTOK + m0 + lc4);
            cpa16(&As[buf^1][lkc1][lc4], Q  + (size_t)(k0+lkc1)*NTOK + n0 + lc4);
            cpa16(&Bs[buf^1][lkc1][lc4], Kp + (size_t)(k0+lkc1)*NTOK + m0 + lc4);
            CPA_COMMIT;
            CPA_WAIT1;
        } else {
            CPA_WAIT0;
        }
        __syncthreads();
        #pragma unroll
        for (int kk = 0; kk < 16; kk += 8) {
            unsigned bfr[4][2];
            #pragma unroll
            for (int nt = 0; nt < 4; nt++) {
                int col = wc + nt*8 + lq;
                bfr[nt][0] = Bs[buf][kk + lr    ][col];
                bfr[nt][1] = Bs[buf][kk + 4 + lr][col];
            }
            #pragma unroll
            for (int mt = 0; mt < 4; mt++) {
                unsigned afr[4];
                int rb = wr + mt*16 + lq;
                afr[0] = As[buf][kk + lr    ][rb];
                afr[1] = As[buf][kk + lr    ][rb + 8];
                afr[2] = As[buf][kk + 4 + lr][rb];
                afr[3] = As[buf][kk + 4 + lr][rb + 8];
                #pragma unroll
                for (int nt = 0; nt < 4; nt++)
                    mma8(acc[mt][nt], afr, bfr[nt]);
            }
        }
        __syncthreads();
    }

    // epilogue: E = tf32round(exp(acc)); fused row-sum atomics
    #pragma unroll
    for (int mt = 0; mt < 4; mt++) {
        const size_t n = n0 + wr + mt*16 + lq;
        float rs0 = 0.f, rs1 = 0.f;
        #pragma unroll
        for (int nt = 0; nt < 4; nt++) {
            const int m = m0 + wc + nt*8 + 2*lr;
            float2 v0, v1;
            v0.x = __uint_as_float(f2tf(__expf(acc[mt][nt][0])));
            v0.y = __uint_as_float(f2tf(__expf(acc[mt][nt][1])));
            v1.x = __uint_as_float(f2tf(__expf(acc[mt][nt][2])));
            v1.y = __uint_as_float(f2tf(__expf(acc[mt][nt][3])));
            rs0 += v0.x + v0.y;
            rs1 += v1.x + v1.y;
            *(float2*)(Eb + n*NTOK + m)     = v0;
            *(float2*)(Eb + (n+8)*NTOK + m) = v1;
        }
        rs0 += __shfl_xor_sync(0xffffffffu, rs0, 1);
        rs0 += __shfl_xor_sync(0xffffffffu, rs0, 2);
        rs1 += __shfl_xor_sync(0xffffffffu, rs1, 1);
        rs1 += __shfl_xor_sync(0xffffffffu, rs1, 2);
        if (lr == 0) {
            atomicAdd(&g_sum[b*NTOK + n],     rs0);
            atomicAdd(&g_sum[b*NTOK + n + 8], rs1);
        }
    }
}

// ---------------- inv[i] = 1/sum[i] ----------------------------------------
__global__ void inv_kernel()
{
    const int i = blockIdx.x * 256 + threadIdx.x;
    if (i < BATCH*NTOK) g_inv[i] = 1.f / g_sum[i];
}

// ---------------- wout[b][m][n] = E[b][n][m] * inv[b][n]  (64x64 f4) -------
__global__ void __launch_bounds__(256)
transpose_scale(const float* __restrict__ E,
                const float* __restrict__ inv,
                float* __restrict__ Wout)
{
    __shared__ float t[64][65];
    __shared__ float is[64];
    const int b = blockIdx.z;
    const float* Eb = E    + (size_t)b*NTOK*NTOK;
    float*       Wb = Wout + (size_t)b*NTOK*NTOK;
    const int m0 = blockIdx.x * 64;
    const int n0 = blockIdx.y * 64;
    const int tx = threadIdx.x & 15;     // 16 x float4 = 64 cols
    const int ty = threadIdx.x >> 4;     // 16 rows
    if (threadIdx.x < 64) is[threadIdx.x] = inv[b*NTOK + n0 + threadIdx.x];
    #pragma unroll
    for (int i = 0; i < 64; i += 16) {
        float4 v = *(const float4*)(Eb + (size_t)(n0+ty+i)*NTOK + m0 + tx*4);
        t[ty+i][tx*4+0] = v.x;
        t[ty+i][tx*4+1] = v.y;
        t[ty+i][tx*4+2] = v.z;
        t[ty+i][tx*4+3] = v.w;
    }
    __syncthreads();
    #pragma unroll
    for (int i = 0; i < 64; i += 16) {
        const int m = ty + i;
        float4 v;
        v.x = t[tx*4+0][m] * is[tx*4+0];
        v.y = t[tx*4+1][m] * is[tx*4+1];
        v.z = t[tx*4+2][m] * is[tx*4+2];
        v.w = t[tx*4+3][m] * is[tx*4+3];
        *(float4*)(Wb + (size_t)(m0+m)*NTOK + n0 + tx*4) = v;
    }
}

// ---------------- hv[c][n] = inv[n] * sum_m V[c][m]*E[n][m]; cp.async ------
__global__ void __launch_bounds__(256)
mm_av_tf32(const float* __restrict__ E)
{
    const int b = blockIdx.z;
    const unsigned* V  = (const unsigned*)g_v + (size_t)b*CCH*NTOK;
    const unsigned* Eb = (const unsigned*)E   + (size_t)b*NTOK*NTOK;
    unsigned* Oh = g_hvh + (size_t)b*CCH*NTOK;
    unsigned* Ol = g_hvl + (size_t)b*CCH*NTOK;
    const int c0 = blockIdx.y * 64;
    const int n0 = blockIdx.x * 128;

    __shared__ unsigned As[2][64][20];    // [buf][c][k]  (V)
    __shared__ unsigned Bs[2][128][20];   // [buf][n][k]  (E)
    __shared__ float    invs[128];

    const int tid  = threadIdx.x;
    const int lane = tid & 31;
    const int wid  = tid >> 5;
    const int wr   = (wid & 1) * 32;
    const int wc   = (wid >> 1) * 32;
    const int lq   = lane >> 2;
    const int lr   = lane & 3;

    // load indices
    const int vc  = tid >> 2,          vk4 = (tid & 3) * 4;
    const int en0 = tid >> 2;                          // s=0 row
    const int en1 = (tid + 256) >> 2;                  // s=1 row

    if (tid < 128) invs[tid] = g_inv[b*NTOK + n0 + tid];

    float acc[2][4][4] = {};

    // prologue: stage 0 (m0i = 0)
    {
        cpa16(&As[0][vc][vk4],  V  + (size_t)(c0+vc)*NTOK + vk4);
        cpa16(&Bs[0][en0][vk4], Eb + (size_t)(n0+en0)*NTOK + vk4);
        cpa16(&Bs[0][en1][vk4], Eb + (size_t)(n0+en1)*NTOK + vk4);
        CPA_COMMIT;
    }

    for (int it = 0; it < 256; it++) {
        const int buf = it & 1;
        if (it + 1 < 256) {
            const int m0i = (it + 1) * 16;
            cpa16(&As[buf^1][vc][vk4],  V  + (size_t)(c0+vc)*NTOK + m0i + vk4);
            cpa16(&Bs[buf^1][en0][vk4], Eb + (size_t)(n0+en0)*NTOK + m0i + vk4);
            cpa16(&Bs[buf^1][en1][vk4], Eb + (size_t)(n0+en1)*NTOK + m0i + vk4);
            CPA_COMMIT;
            CPA_WAIT1;
        } else {
            CPA_WAIT0;
        }
        __syncthreads();
        #pragma unroll
        for (int kk = 0; kk < 16; kk += 8) {
            unsigned bfr[4][2];
            #pragma unroll
            for (int nt = 0; nt < 4; nt++) {
                int col = wc + nt*8 + lq;
                bfr[nt][0] = Bs[buf][col][kk + lr];
                bfr[nt][1] = Bs[buf][col][kk + 4 + lr];
            }
            #pragma unroll
            for (int mt = 0; mt < 2; mt++) {
                unsigned afr[4];
                int rb = wr + mt*16 + lq;
                afr[0] = As[buf][rb    ][kk + lr];
                afr[1] = As[buf][rb + 8][kk + lr];
                afr[2] = As[buf][rb    ][kk + 4 + lr];
                afr[3] = As[buf][rb + 8][kk + 4 + lr];
                #pragma unroll
                for (int nt = 0; nt < 4; nt++)
                    mma8(acc[mt][nt], afr, bfr[nt]);
            }
        }
        __syncthreads();
    }

    #pragma unroll
    for (int mt = 0; mt < 2; mt++) {
        const int row = wr + mt*16 + lq;
        #pragma unroll
        for (int nt = 0; nt < 4; nt++) {
            const int nl = wc + nt*8 + 2*lr;
            const float i0 = invs[nl], i1 = invs[nl+1];
            float vv[4];
            vv[0] = acc[mt][nt][0] * i0;  vv[1] = acc[mt][nt][1] * i1;
            vv[2] = acc[mt][nt][2] * i0;  vv[3] = acc[mt][nt][3] * i1;
            unsigned h0 = f2tf(vv[0]), h1 = f2tf(vv[1]);
            unsigned h2 = f2tf(vv[2]), h3 = f2tf(vv[3]);
            uint2 uh0 = {h0, h1}, uh1 = {h2, h3};
            uint2 ul0 = {f2tf(vv[0]-__uint_as_float(h0)), f2tf(vv[1]-__uint_as_float(h1))};
            uint2 ul1 = {f2tf(vv[2]-__uint_as_float(h2)), f2tf(vv[3]-__uint_as_float(h3))};
            *(uint2*)(Oh + (size_t)(c0+row  )*NTOK + n0 + nl) = uh0;
            *(uint2*)(Oh + (size_t)(c0+row+8)*NTOK + n0 + nl) = uh1;
            *(uint2*)(Ol + (size_t)(c0+row  )*NTOK + n0 + nl) = ul0;
            *(uint2*)(Ol + (size_t)(c0+row+8)*NTOK + n0 + nl) = ul1;
        }
    }
}

// ---------------------------------------------------------------------------
extern "C" void kernel_launch(void* const* d_in, const int* in_sizes, int n_in,
                              void* d_out, int out_size)
{
    const float* x     = (const float*)d_in[0];
    const float* gamma = (const float*)d_in[1];
    const float* beta  = (const float*)d_in[2];
    const float* wq = (const float*)d_in[3];  const float* bq = (const float*)d_in[4];
    const float* wk = (const float*)d_in[5];  const float* bk = (const float*)d_in[6];
    const float* wv = (const float*)d_in[7];  const float* bv = (const float*)d_in[8];
    const float* wp = (const float*)d_in[9];  const float* bp = (const float*)d_in[10];

    float* out  = (float*)d_out;                              // (2,256,4096)
    float* wout = out + (size_t)BATCH*CCH*NTOK;               // (2,4096,4096)

    float *p_p, *p_inv;
    cudaGetSymbolAddress((void**)&p_p,   g_p);
    cudaGetSymbolAddress((void**)&p_inv, g_inv);

    // 0. zero accumulators; transpose+split weights (tiny)
    zero_kernel<<<33, 256>>>();
    prep_w<<<dim3(CCH, 4), CCH>>>(wq, wk, wv, wp);

    // 1. GroupNorm (two-pass; pass 2 writes tf32 hi/lo directly)
    gn_stats<<<BATCH*GRP*8, 256>>>(x);
    gn_apply<<<BATCH*CCH, 256>>>(x, gamma, beta);

    // 2. fused q/k/v projections (cvt-free 3xTF32 split; q pre-scaled)
    mm_qkv<<<dim3(32, 6, BATCH), 256>>>(bq, bk, bv);

    // 3. E = exp(q^T k) with fused row sums (cp.async pipelined)
    mm_s_tf32<<<dim3(32, 32, BATCH), 256>>>(p_p);

    // 4. reciprocal of row sums
    inv_kernel<<<32, 256>>>();

    // 5. returned attention = normalize + transpose (64x64 float4 tiles)
    if (out_size >= (int)((size_t)BATCH*CCH*NTOK + (size_t)BATCH*NTOK*NTOK))
        transpose_scale<<<dim3(64, 64, BATCH), 256>>>(p_p, p_inv, wout);

    // 6. hv = (v . E^T) * inv  (cp.async pipelined)
    mm_av_tf32<<<dim3(32, 4, BATCH), 256>>>(p_p);

    // 7. out = x + (wp . hv + bp)  (cvt-free 3xTF32 split)
    mm_proj<<<dim3(32, 2, BATCH), 256>>>(bp, x, out);
}

// round 13
// speedup vs baseline: 3.4116x; 1.0731x over previous
#include <cuda_runtime.h>
#include <cstdint>

#define NTOK 4096            // d*h*w = 16^3
#define CCH  256             // channels
#define BATCH 2
#define GRP  32
#define CPG  (CCH/GRP)       // 8
#define EPSV 1e-6f
#define SCALE 0.0625f        // 256^-0.5

// ---------------- scratch (device globals; no allocation allowed) ----------
__device__ unsigned g_hnh[BATCH*CCH*NTOK];        // tf32 split of groupnorm out
__device__ unsigned g_hnl[BATCH*CCH*NTOK];
__device__ float    g_q [BATCH*CCH*NTOK];         // tf32-rounded, pre-scaled
__device__ float    g_k [BATCH*CCH*NTOK];         // tf32-rounded
__device__ float    g_v [BATCH*CCH*NTOK];         // tf32-rounded
__device__ unsigned g_hvh[BATCH*CCH*NTOK];        // tf32 split of v.attn^T
__device__ unsigned g_hvl[BATCH*CCH*NTOK];
__device__ unsigned g_wth[4*CCH*CCH];             // W transposed [k][o], tf32 hi
__device__ unsigned g_wtl[4*CCH*CCH];             //                      tf32 lo
__device__ float    g_p [(size_t)BATCH*NTOK*NTOK]; // exp(S), tf32-rounded
__device__ float    g_sum[BATCH*NTOK];
__device__ float    g_inv[BATCH*NTOK];
__device__ float    g_stats[BATCH*GRP*2];

// ---------------- helpers --------------------------------------------------
__device__ __forceinline__ unsigned f2tf(float f) {
    unsigned u;
    asm("cvt.rna.tf32.f32 %0, %1;" : "=r"(u) : "f"(f));
    return u;
}

__device__ __forceinline__ void mma8(float* c, const unsigned* a, const unsigned* b) {
    asm volatile(
        "mma.sync.aligned.m16n8k8.row.col.f32.tf32.tf32.f32 "
        "{%0,%1,%2,%3}, {%4,%5,%6,%7}, {%8,%9}, {%0,%1,%2,%3};\n"
        : "+f"(c[0]), "+f"(c[1]), "+f"(c[2]), "+f"(c[3])
        : "r"(a[0]), "r"(a[1]), "r"(a[2]), "r"(a[3]),
          "r"(b[0]), "r"(b[1]));
}

__device__ __forceinline__ void cpa16(void* smem, const void* gmem) {
    unsigned saddr = (unsigned)__cvta_generic_to_shared(smem);
    asm volatile("cp.async.cg.shared.global [%0], [%1], 16;\n" :: "r"(saddr), "l"(gmem));
}
#define CPA_COMMIT asm volatile("cp.async.commit_group;\n" ::: "memory")
#define CPA_WAIT1  asm volatile("cp.async.wait_group 1;\n" ::: "memory")
#define CPA_WAIT0  asm volatile("cp.async.wait_group 0;\n" ::: "memory")

// ---------------- zero accumulators ---------------------------------------
__global__ void zero_kernel()
{
    const int i = blockIdx.x * 256 + threadIdx.x;
    if (i < BATCH*NTOK) g_sum[i] = 0.f;
    if (i < BATCH*GRP*2) g_stats[i] = 0.f;
}

// ---------------- W prep: transpose to [k][o] and tf32-split ---------------
__global__ void prep_w(const float* __restrict__ w0, const float* __restrict__ w1,
                       const float* __restrict__ w2, const float* __restrict__ w3)
{
    const int m = blockIdx.y;
    const float* W = (m == 0) ? w0 : (m == 1) ? w1 : (m == 2) ? w2 : w3;
    const int o = blockIdx.x;
    const int k = threadIdx.x;
    const float f = W[o*CCH + k];
    const unsigned h = f2tf(f);
    g_wth[m*CCH*CCH + k*CCH + o] = h;
    g_wtl[m*CCH*CCH + k*CCH + o] = f2tf(f - __uint_as_float(h));
}

// ---------------- GroupNorm pass 1: partial stats --------------------------
__global__ void gn_stats(const float* __restrict__ x)
{
    const int gidx  = blockIdx.x >> 3;
    const int chunk = blockIdx.x & 7;
    const float* xp = x + (size_t)gidx*CPG*NTOK + chunk*NTOK;
    const int tid = threadIdx.x;

    float s = 0.f, ss = 0.f;
    #pragma unroll
    for (int i = tid*4; i < NTOK; i += 1024) {
        float4 t = *(const float4*)(xp + i);
        s  += t.x + t.y + t.z + t.w;
        ss += t.x*t.x + t.y*t.y + t.z*t.z + t.w*t.w;
    }
    __shared__ float rs[256], rq[256];
    rs[tid] = s; rq[tid] = ss;
    __syncthreads();
    for (int off = 128; off; off >>= 1) {
        if (tid < off) { rs[tid] += rs[tid+off]; rq[tid] += rq[tid+off]; }
        __syncthreads();
    }
    if (tid == 0) {
        atomicAdd(&g_stats[2*gidx],   rs[0]);
        atomicAdd(&g_stats[2*gidx+1], rq[0]);
    }
}

// ---------------- GroupNorm pass 2: normalize + tf32-split write -----------
__global__ void gn_apply(const float* __restrict__ x,
                         const float* __restrict__ gamma,
                         const float* __restrict__ beta)
{
    const int c    = blockIdx.x & 255;
    const int gidx = (blockIdx.x >> 8) * GRP + (c >> 3);
    const float mu   = g_stats[2*gidx]   * (1.f/32768.f);
    const float var  = g_stats[2*gidx+1] * (1.f/32768.f) - mu*mu;
    const float rstd = rsqrtf(var + EPSV);
    const float ga = gamma[c]*rstd, be = beta[c];

    const size_t base = (size_t)blockIdx.x * NTOK;
    const int i = threadIdx.x * 4;
    #pragma unroll
    for (int s = 0; s < 4; s++) {
        float4 t = *(const float4*)(x + base + i + s*1024);
        float f[4];
        f[0] = (t.x - mu)*ga + be;
        f[1] = (t.y - mu)*ga + be;
        f[2] = (t.z - mu)*ga + be;
        f[3] = (t.w - mu)*ga + be;
        uint4 uh, ul;
        uh.x = f2tf(f[0]); ul.x = f2tf(f[0] - __uint_as_float(uh.x));
        uh.y = f2tf(f[1]); ul.y = f2tf(f[1] - __uint_as_float(uh.y));
        uh.z = f2tf(f[2]); ul.z = f2tf(f[2] - __uint_as_float(uh.z));
        uh.w = f2tf(f[3]); ul.w = f2tf(f[3] - __uint_as_float(uh.w));
        *(uint4*)(g_hnh + base + i + s*1024) = uh;
        *(uint4*)(g_hnl + base + i + s*1024) = ul;
    }
}

// ---------------- fused q/k/v projection, cvt-free 3xTF32 split ------------
__global__ void __launch_bounds__(256)
mm_qkv(const float* __restrict__ bq,
       const float* __restrict__ bk,
       const float* __restrict__ bv)
{
    const int b   = blockIdx.z;
    const int sel = blockIdx.y >> 1;
    const int o0  = (blockIdx.y & 1) * 128;
    const int n0  = blockIdx.x * 128;

    const unsigned* Wh  = g_wth + sel*CCH*CCH;
    const unsigned* Wl  = g_wtl + sel*CCH*CCH;
    const unsigned* Bhg = g_hnh + (size_t)b*CCH*NTOK;
    const unsigned* Blg = g_hnl + (size_t)b*CCH*NTOK;
    float* O = ((sel == 0) ? g_q : (sel == 1) ? g_k : g_v) + (size_t)b*CCH*NTOK;
    const float* bias = (sel == 0) ? bq : (sel == 1) ? bk : bv;
    const float outScale = (sel == 0) ? SCALE : 1.f;

    __shared__ unsigned Ah[16][136], Al[16][136];
    __shared__ unsigned Bh[16][136], Bl[16][136];

    const int tid  = threadIdx.x;
    const int lane = tid & 31;
    const int wid  = tid >> 5;
    const int wr   = (wid & 1) * 64;
    const int wc   = (wid >> 1) * 32;
    const int lq   = lane >> 2;
    const int lr   = lane & 3;

    float acc[4][4][4] = {};

    for (int k0 = 0; k0 < CCH; k0 += 16) {
        #pragma unroll
        for (int s = 0; s < 2; s++) {
            int idx = tid + s*256;
            int kc = idx >> 5, c4 = (idx & 31) * 4;
            *(uint4*)&Ah[kc][c4] = *(const uint4*)(Wh  + (k0+kc)*CCH  + o0 + c4);
            *(uint4*)&Al[kc][c4] = *(const uint4*)(Wl  + (k0+kc)*CCH  + o0 + c4);
            *(uint4*)&Bh[kc][c4] = *(const uint4*)(Bhg + (size_t)(k0+kc)*NTOK + n0 + c4);
            *(uint4*)&Bl[kc][c4] = *(const uint4*)(Blg + (size_t)(k0+kc)*NTOK + n0 + c4);
        }
        __syncthreads();
        #pragma unroll
        for (int kk = 0; kk < 16; kk += 8) {
            unsigned bh[4][2], bl[4][2];
            #pragma unroll
            for (int nt = 0; nt < 4; nt++) {
                int col = wc + nt*8 + lq;
                bh[nt][0] = Bh[kk + lr    ][col];
                bh[nt][1] = Bh[kk + 4 + lr][col];
                bl[nt][0] = Bl[kk + lr    ][col];
                bl[nt][1] = Bl[kk + 4 + lr][col];
            }
            #pragma unroll
            for (int mt = 0; mt < 4; mt++) {
                unsigned ah[4], al[4];
                int rb = wr + mt*16 + lq;
                ah[0] = Ah[kk + lr    ][rb];   ah[1] = Ah[kk + lr    ][rb + 8];
                ah[2] = Ah[kk + 4 + lr][rb];   ah[3] = Ah[kk + 4 + lr][rb + 8];
                al[0] = Al[kk + lr    ][rb];   al[1] = Al[kk + lr    ][rb + 8];
                al[2] = Al[kk + 4 + lr][rb];   al[3] = Al[kk + 4 + lr][rb + 8];
                #pragma unroll
                for (int nt = 0; nt < 4; nt++) {
                    mma8(acc[mt][nt], ah, bh[nt]);
                    mma8(acc[mt][nt], ah, bl[nt]);
                    mma8(acc[mt][nt], al, bh[nt]);
                }
            }
        }
        __syncthreads();
    }

    #pragma unroll
    for (int mt = 0; mt < 4; mt++) {
        const int o = o0 + wr + mt*16 + lq;
        const float bi0 = bias[o], bi1 = bias[o+8];
        #pragma unroll
        for (int nt = 0; nt < 4; nt++) {
            const int n = n0 + wc + nt*8 + 2*lr;
            float2 v0, v1;
            v0.x = __uint_as_float(f2tf((acc[mt][nt][0] + bi0) * outScale));
            v0.y = __uint_as_float(f2tf((acc[mt][nt][1] + bi0) * outScale));
            v1.x = __uint_as_float(f2tf((acc[mt][nt][2] + bi1) * outScale));
            v1.y = __uint_as_float(f2tf((acc[mt][nt][3] + bi1) * outScale));
            *(float2*)(O + (size_t)o*NTOK + n)     = v0;
            *(float2*)(O + (size_t)(o+8)*NTOK + n) = v1;
        }
    }
}

// ---------------- output projection + residual, cvt-free 3xTF32 split ------
__global__ void __launch_bounds__(256)
mm_proj(const float* __restrict__ bias,
        const float* __restrict__ Xbase,
        float* __restrict__ Obase)
{
    const int b  = blockIdx.z;
    const unsigned* Wh  = g_wth + 3*CCH*CCH;
    const unsigned* Wl  = g_wtl + 3*CCH*CCH;
    const unsigned* Bhg = g_hvh + (size_t)b*CCH*NTOK;
    const unsigned* Blg = g_hvl + (size_t)b*CCH*NTOK;
    const float* X = Xbase + (size_t)b*CCH*NTOK;
    float*       O = Obase + (size_t)b*CCH*NTOK;
    const int o0 = blockIdx.y * 128;
    const int n0 = blockIdx.x * 128;

    __shared__ unsigned Ah[16][136], Al[16][136];
    __shared__ unsigned Bh[16][136], Bl[16][136];

    const int tid  = threadIdx.x;
    const int lane = tid & 31;
    const int wid  = tid >> 5;
    const int wr   = (wid & 1) * 64;
    const int wc   = (wid >> 1) * 32;
    const int lq   = lane >> 2;
    const int lr   = lane & 3;

    float acc[4][4][4] = {};

    for (int k0 = 0; k0 < CCH; k0 += 16) {
        #pragma unroll
        for (int s = 0; s < 2; s++) {
            int idx = tid + s*256;
            int kc = idx >> 5, c4 = (idx & 31) * 4;
            *(uint4*)&Ah[kc][c4] = *(const uint4*)(Wh  + (k0+kc)*CCH  + o0 + c4);
            *(uint4*)&Al[kc][c4] = *(const uint4*)(Wl  + (k0+kc)*CCH  + o0 + c4);
            *(uint4*)&Bh[kc][c4] = *(const uint4*)(Bhg + (size_t)(k0+kc)*NTOK + n0 + c4);
            *(uint4*)&Bl[kc][c4] = *(const uint4*)(Blg + (size_t)(k0+kc)*NTOK + n0 + c4);
        }
        __syncthreads();
        #pragma unroll
        for (int kk = 0; kk < 16; kk += 8) {
            unsigned bh[4][2], bl[4][2];
            #pragma unroll
            for (int nt = 0; nt < 4; nt++) {
                int col = wc + nt*8 + lq;
                bh[nt][0] = Bh[kk + lr    ][col];
                bh[nt][1] = Bh[kk + 4 + lr][col];
                bl[nt][0] = Bl[kk + lr    ][col];
                bl[nt][1] = Bl[kk + 4 + lr][col];
            }
            #pragma unroll
            for (int mt = 0; mt < 4; mt++) {
                unsigned ah[4], al[4];
                int rb = wr + mt*16 + lq;
                ah[0] = Ah[kk + lr    ][rb];   ah[1] = Ah[kk + lr    ][rb + 8];
                ah[2] = Ah[kk + 4 + lr][rb];   ah[3] = Ah[kk + 4 + lr][rb + 8];
                al[0] = Al[kk + lr    ][rb];   al[1] = Al[kk + lr    ][rb + 8];
                al[2] = Al[kk + 4 + lr][rb];   al[3] = Al[kk + 4 + lr][rb + 8];
                #pragma unroll
                for (int nt = 0; nt < 4; nt++) {
                    mma8(acc[mt][nt], ah, bh[nt]);
                    mma8(acc[mt][nt], ah, bl[nt]);
                    mma8(acc[mt][nt], al, bh[nt]);
                }
            }
        }
        __syncthreads();
    }

    #pragma unroll
    for (int mt = 0; mt < 4; mt++) {
        const int o = o0 + wr + mt*16 + lq;
        const float bi0 = bias[o], bi1 = bias[o+8];
        #pragma unroll
        for (int nt = 0; nt < 4; nt++) {
            const int n = n0 + wc + nt*8 + 2*lr;
            float2 x0 = *(const float2*)(X + (size_t)o*NTOK + n);
            float2 x1 = *(const float2*)(X + (size_t)(o+8)*NTOK + n);
            float2 v0, v1;
            v0.x = acc[mt][nt][0] + bi0 + x0.x;  v0.y = acc[mt][nt][1] + bi0 + x0.y;
            v1.x = acc[mt][nt][2] + bi1 + x1.x;  v1.y = acc[mt][nt][3] + bi1 + x1.y;
            *(float2*)(O + (size_t)o*NTOK + n)     = v0;
            *(float2*)(O + (size_t)(o+8)*NTOK + n) = v1;
        }
    }
}

// ---------------- E[n][m] = exp(q^T k); cp.async double-buffered -----------
__global__ void __launch_bounds__(256, 2)
mm_s_tf32(float* __restrict__ E)
{
    const int b = blockIdx.z;
    const unsigned* Q  = (const unsigned*)g_q + (size_t)b*CCH*NTOK;
    const unsigned* Kp = (const unsigned*)g_k + (size_t)b*CCH*NTOK;
    float*          Eb = E + (size_t)b*NTOK*NTOK;
    const int n0 = blockIdx.y * 128;
    const int m0 = blockIdx.x * 128;

    __shared__ unsigned As[2][16][136];   // [buf][k][n]
    __shared__ unsigned Bs[2][16][136];   // [buf][k][m]

    const int tid  = threadIdx.x;
    const int lane = tid & 31;
    const int wid  = tid >> 5;
    const int wr   = (wid & 1) * 64;
    const int wc   = (wid >> 1) * 32;
    const int lq   = lane >> 2;
    const int lr   = lane & 3;

    const int lkc0 = tid >> 5,        lc4 = (tid & 31) * 4;
    const int lkc1 = (tid + 256) >> 5;

    float acc[4][4][4] = {};

    {
        cpa16(&As[0][lkc0][lc4], Q  + (size_t)lkc0*NTOK + n0 + lc4);
        cpa16(&Bs[0][lkc0][lc4], Kp + (size_t)lkc0*NTOK + m0 + lc4);
        cpa16(&As[0][lkc1][lc4], Q  + (size_t)lkc1*NTOK + n0 + lc4);
        cpa16(&Bs[0][lkc1][lc4], Kp + (size_t)lkc1*NTOK + m0 + lc4);
        CPA_COMMIT;
    }

    for (int it = 0; it < 16; it++) {
        const int buf = it & 1;
        if (it + 1 < 16) {
            const int k0 = (it + 1) * 16;
            cpa16(&As[buf^1][lkc0][lc4], Q  + (size_t)(k0+lkc0)*NTOK + n0 + lc4);
            cpa16(&Bs[buf^1][lkc0][lc4], Kp + (size_t)(k0+lkc0)*NTOK + m0 + lc4);
            cpa16(&As[buf^1][lkc1][lc4], Q  + (size_t)(k0+lkc1)*NTOK + n0 + lc4);
            cpa16(&Bs[buf^1][lkc1][lc4], Kp + (size_t)(k0+lkc1)*NTOK + m0 + lc4);
            CPA_COMMIT;
            CPA_WAIT1;
        } else {
            CPA_WAIT0;
        }
        __syncthreads();
        #pragma unroll
        for (int kk = 0; kk < 16; kk += 8) {
            unsigned bfr[4][2];
            #pragma unroll
            for (int nt = 0; nt < 4; nt++) {
                int col = wc + nt*8 + lq;
                bfr[nt][0] = Bs[buf][kk + lr    ][col];
                bfr[nt][1] = Bs[buf][kk + 4 + lr][col];
            }
            #pragma unroll
            for (int mt = 0; mt < 4; mt++) {
                unsigned afr[4];
                int rb = wr + mt*16 + lq;
                afr[0] = As[buf][kk + lr    ][rb];
                afr[1] = As[buf][kk + lr    ][rb + 8];
                afr[2] = As[buf][kk + 4 + lr][rb];
                afr[3] = As[buf][kk + 4 + lr][rb + 8];
                #pragma unroll
                for (int nt = 0; nt < 4; nt++)
                    mma8(acc[mt][nt], afr, bfr[nt]);
            }
        }
        __syncthreads();
    }

    #pragma unroll
    for (int mt = 0; mt < 4; mt++) {
        const size_t n = n0 + wr + mt*16 + lq;
        float rs0 = 0.f, rs1 = 0.f;
        #pragma unroll
        for (int nt = 0; nt < 4; nt++) {
            const int m = m0 + wc + nt*8 + 2*lr;
            float2 v0, v1;
            v0.x = __uint_as_float(f2tf(__expf(acc[mt][nt][0])));
            v0.y = __uint_as_float(f2tf(__expf(acc[mt][nt][1])));
            v1.x = __uint_as_float(f2tf(__expf(acc[mt][nt][2])));
            v1.y = __uint_as_float(f2tf(__expf(acc[mt][nt][3])));
            rs0 += v0.x + v0.y;
            rs1 += v1.x + v1.y;
            *(float2*)(Eb + n*NTOK + m)     = v0;
            *(float2*)(Eb + (n+8)*NTOK + m) = v1;
        }
        rs0 += __shfl_xor_sync(0xffffffffu, rs0, 1);
        rs0 += __shfl_xor_sync(0xffffffffu, rs0, 2);
        rs1 += __shfl_xor_sync(0xffffffffu, rs1, 1);
        rs1 += __shfl_xor_sync(0xffffffffu, rs1, 2);
        if (lr == 0) {
            atomicAdd(&g_sum[b*NTOK + n],     rs0);
            atomicAdd(&g_sum[b*NTOK + n + 8], rs1);
        }
    }
}

// ---------------- inv[i] = 1/sum[i] ----------------------------------------
__global__ void inv_kernel()
{
    const int i = blockIdx.x * 256 + threadIdx.x;
    if (i < BATCH*NTOK) g_inv[i] = 1.f / g_sum[i];
}

// ---------------- hv[c][n] = inv[n]*sum_m V[c][m]*E[n][m]; 3-stage ---------
// fused: CTAs also emit wout[m][n] = E[n][m]*inv[n] from the staged E tiles
// (iteration it written by c-block with blockIdx.y == it&3)
__global__ void __launch_bounds__(256)
mm_av_tf32(const float* __restrict__ E, float* __restrict__ WoutBase, int doW)
{
    const int b = blockIdx.z;
    const unsigned* V  = (const unsigned*)g_v + (size_t)b*CCH*NTOK;
    const unsigned* Eb = (const unsigned*)E   + (size_t)b*NTOK*NTOK;
    unsigned* Oh = g_hvh + (size_t)b*CCH*NTOK;
    unsigned* Ol = g_hvl + (size_t)b*CCH*NTOK;
    float*    Wb = WoutBase + (size_t)b*NTOK*NTOK;
    const int c0 = blockIdx.y * 64;
    const int n0 = blockIdx.x * 128;
    const int myPhase = blockIdx.y;    // it&3 == myPhase -> this CTA writes wout

    __shared__ unsigned As[3][64][20];    // [stage][c][k]  (V)
    __shared__ unsigned Bs[3][128][20];   // [stage][n][k]  (E)
    __shared__ float    invs[128];

    const int tid  = threadIdx.x;
    const int lane = tid & 31;
    const int wid  = tid >> 5;
    const int wr   = (wid & 1) * 32;
    const int wc   = (wid >> 1) * 32;
    const int lq   = lane >> 2;
    const int lr   = lane & 3;

    const int vc  = tid >> 2,  vk4 = (tid & 3) * 4;
    const int en0 = tid >> 2;
    const int en1 = (tid + 256) >> 2;

    // wout-store mapping: thread t -> column n=t&127, k-half (t>>7)*8
    const int tn = tid & 127;
    const int tk = (tid >> 7) * 8;

    if (tid < 128) invs[tid] = g_inv[b*NTOK + n0 + tid];

    float acc[2][4][4] = {};

    // prologue: stages 0, 1
    #pragma unroll
    for (int s = 0; s < 2; s++) {
        const int m0i = s * 16;
        cpa16(&As[s][vc][vk4],  V  + (size_t)(c0+vc)*NTOK + m0i + vk4);
        cpa16(&Bs[s][en0][vk4], Eb + (size_t)(n0+en0)*NTOK + m0i + vk4);
        cpa16(&Bs[s][en1][vk4], Eb + (size_t)(n0+en1)*NTOK + m0i + vk4);
        CPA_COMMIT;
    }

    for (int it = 0; it < 256; it++) {
        const int buf = it % 3;
        if (it + 1 < 256) { CPA_WAIT1; } else { CPA_WAIT0; }
        __syncthreads();
        // prefetch stage it+2 (overwrites buffer of it-1; all warps are past it-1)
        if (it + 2 < 256) {
            const int st  = (it + 2) % 3;
            const int m0i = (it + 2) * 16;
            cpa16(&As[st][vc][vk4],  V  + (size_t)(c0+vc)*NTOK + m0i + vk4);
            cpa16(&Bs[st][en0][vk4], Eb + (size_t)(n0+en0)*NTOK + m0i + vk4);
            cpa16(&Bs[st][en1][vk4], Eb + (size_t)(n0+en1)*NTOK + m0i + vk4);
            CPA_COMMIT;
        }
        #pragma unroll
        for (int kk = 0; kk < 16; kk += 8) {
            unsigned bfr[4][2];
            #pragma unroll
            for (int nt = 0; nt < 4; nt++) {
                int col = wc + nt*8 + lq;
                bfr[nt][0] = Bs[buf][col][kk + lr];
                bfr[nt][1] = Bs[buf][col][kk + 4 + lr];
            }
            #pragma unroll
            for (int mt = 0; mt < 2; mt++) {
                unsigned afr[4];
                int rb = wr + mt*16 + lq;
                afr[0] = As[buf][rb    ][kk + lr];
                afr[1] = As[buf][rb + 8][kk + lr];
                afr[2] = As[buf][rb    ][kk + 4 + lr];
                afr[3] = As[buf][rb + 8][kk + 4 + lr];
                #pragma unroll
                for (int nt = 0; nt < 4; nt++)
                    mma8(acc[mt][nt], afr, bfr[nt]);
            }
        }
        // fused transposed wout write from the staged E tile
        if (doW && (it & 3) == myPhase) {
            const float iv = invs[tn];
            float* wrow = Wb + (size_t)(it*16) * NTOK + n0 + tn;
            #pragma unroll
            for (int j = 0; j < 8; j++) {
                float e = __uint_as_float(Bs[buf][tn][tk + j]);
                wrow[(size_t)(tk + j) * NTOK] = e * iv;
            }
        }
    }

    #pragma unroll
    for (int mt = 0; mt < 2; mt++) {
        const int row = wr + mt*16 + lq;
        #pragma unroll
        for (int nt = 0; nt < 4; nt++) {
            const int nl = wc + nt*8 + 2*lr;
            const float i0 = invs[nl], i1 = invs[nl+1];
            float vv[4];
            vv[0] = acc[mt][nt][0] * i0;  vv[1] = acc[mt][nt][1] * i1;
            vv[2] = acc[mt][nt][2] * i0;  vv[3] = acc[mt][nt][3] * i1;
            unsigned h0 = f2tf(vv[0]), h1 = f2tf(vv[1]);
            unsigned h2 = f2tf(vv[2]), h3 = f2tf(vv[3]);
            uint2 uh0 = {h0, h1}, uh1 = {h2, h3};
            uint2 ul0 = {f2tf(vv[0]-__uint_as_float(h0)), f2tf(vv[1]-__uint_as_float(h1))};
            uint2 ul1 = {f2tf(vv[2]-__uint_as_float(h2)), f2tf(vv[3]-__uint_as_float(h3))};
            *(uint2*)(Oh + (size_t)(c0+row  )*NTOK + n0 + nl) = uh0;
            *(uint2*)(Oh + (size_t)(c0+row+8)*NTOK + n0 + nl) = uh1;
            *(uint2*)(Ol + (size_t)(c0+row  )*NTOK + n0 + nl) = ul0;
            *(uint2*)(Ol + (size_t)(c0+row+8)*NTOK + n0 + nl) = ul1;
        }
    }
}

// ---------------------------------------------------------------------------
extern "C" void kernel_launch(void* const* d_in, const int* in_sizes, int n_in,
                              void* d_out, int out_size)
{
    const float* x     = (const float*)d_in[0];
    const float* gamma = (const float*)d_in[1];
    const float* beta  = (const float*)d_in[2];
    const float* wq = (const float*)d_in[3];  const float* bq = (const float*)d_in[4];
    const float* wk = (const float*)d_in[5];  const float* bk = (const float*)d_in[6];
    const float* wv = (const float*)d_in[7];  const float* bv = (const float*)d_in[8];
    const float* wp = (const float*)d_in[9];  const float* bp = (const float*)d_in[10];

    float* out  = (float*)d_out;                              // (2,256,4096)
    float* wout = out + (size_t)BATCH*CCH*NTOK;               // (2,4096,4096)

    float *p_p;
    cudaGetSymbolAddress((void**)&p_p, g_p);

    const int doW = out_size >= (int)((size_t)BATCH*CCH*NTOK + (size_t)BATCH*NTOK*NTOK);

    // 0. zero accumulators; transpose+split weights (tiny)
    zero_kernel<<<33, 256>>>();
    prep_w<<<dim3(CCH, 4), CCH>>>(wq, wk, wv, wp);

    // 1. GroupNorm (two-pass; pass 2 writes tf32 hi/lo directly)
    gn_stats<<<BATCH*GRP*8, 256>>>(x);
    gn_apply<<<BATCH*CCH, 256>>>(x, gamma, beta);

    // 2. fused q/k/v projections (cvt-free 3xTF32 split; q pre-scaled)
    mm_qkv<<<dim3(32, 6, BATCH), 256>>>(bq, bk, bv);

    // 3. E = exp(q^T k) with fused row sums (cp.async pipelined)
    mm_s_tf32<<<dim3(32, 32, BATCH), 256>>>(p_p);

    // 4. reciprocal of row sums
    inv_kernel<<<32, 256>>>();

    // 5+6. hv = (v . E^T) * inv  AND  wout = E^T * inv (fused, 3-stage pipe)
    mm_av_tf32<<<dim3(32, 4, BATCH), 256>>>(p_p, wout, doW);

    // 7. out = x + (wp . hv + bp)  (cvt-free 3xTF32 split)
    mm_proj<<<dim3(32, 2, BATCH), 256>>>(bp, x, out);
}